// round 1
// baseline (speedup 1.0000x reference)
#include <cuda_runtime.h>

// ---------------------------------------------------------------------------
// Problem constants
// ---------------------------------------------------------------------------
#define BATCH 4
#define LTOT  13294
#define MROWS (BATCH * LTOT)   // 53176
#define DMODEL 256
#define DFFN   1024
#define NHEAD  8
#define NLVL   4
#define NPTS   4
#define DHEAD  32

// ---------------------------------------------------------------------------
// Scratch (device globals; no runtime allocation allowed)
// ---------------------------------------------------------------------------
__device__ float g_q   [MROWS * DMODEL];
__device__ float g_v   [MROWS * DMODEL];
__device__ float g_off [MROWS * DMODEL];
__device__ float g_aw  [MROWS * 128];
__device__ float g_samp[MROWS * DMODEL];
__device__ float g_tmp [MROWS * DMODEL];
__device__ float g_x   [MROWS * DMODEL];
__device__ float g_h1  [MROWS * DFFN];

// ---------------------------------------------------------------------------
// Elementwise add: q = src + pos  (float4 vectorized)
// ---------------------------------------------------------------------------
__global__ void add_k(const float4* __restrict__ a, const float4* __restrict__ b,
                      float4* __restrict__ c, int n4) {
    int i = blockIdx.x * blockDim.x + threadIdx.x;
    if (i >= n4) return;
    float4 x = a[i], y = b[i];
    c[i] = make_float4(x.x + y.x, x.y + y.y, x.z + y.z, x.w + y.w);
}

// ---------------------------------------------------------------------------
// SGEMM: C[M,N] = A[M,K] @ W[K,N] + bias (+ residual) (+ relu)
// 128x128 block tile, BK=8, 256 threads, 8x8 per-thread microtile.
// Assumes N % 128 == 0 and K % 8 == 0 (true here: N in {128,256,1024}, K in {256,1024}).
// MODE: 0 = bias, 1 = bias+relu, 2 = bias+residual
// ---------------------------------------------------------------------------
template <int MODE>
__global__ __launch_bounds__(256)
void sgemm_k(const float* __restrict__ A, const float* __restrict__ W,
             const float* __restrict__ bias, const float* __restrict__ res,
             float* __restrict__ C, int M, int N, int K) {
    __shared__ float As[8][128];
    __shared__ float Bs[8][128];

    const int tid = threadIdx.x;
    const int block_row = blockIdx.y * 128;
    const int block_col = blockIdx.x * 128;

    // A tile loader: 128 rows x 8 cols, one float4 per thread
    const int arow = tid >> 1;            // 0..127
    const int acol = (tid & 1) * 4;       // 0 or 4
    // B tile loader: 8 rows x 128 cols, one float4 per thread
    const int brow = tid >> 5;            // 0..7
    const int bcol = (tid & 31) * 4;      // 0..124

    const int ty = tid >> 4;              // 0..15
    const int tx = tid & 15;              // 0..15

    float acc[8][8];
#pragma unroll
    for (int i = 0; i < 8; i++)
#pragma unroll
        for (int j = 0; j < 8; j++) acc[i][j] = 0.f;

    for (int k0 = 0; k0 < K; k0 += 8) {
        // load A tile (guard M), store transposed As[k][row]
        float4 av = make_float4(0.f, 0.f, 0.f, 0.f);
        int gr = block_row + arow;
        if (gr < M)
            av = *reinterpret_cast<const float4*>(&A[(size_t)gr * K + k0 + acol]);
        As[acol + 0][arow] = av.x;
        As[acol + 1][arow] = av.y;
        As[acol + 2][arow] = av.z;
        As[acol + 3][arow] = av.w;
        // load B tile
        float4 bv = *reinterpret_cast<const float4*>(
            &W[(size_t)(k0 + brow) * N + block_col + bcol]);
        *reinterpret_cast<float4*>(&Bs[brow][bcol]) = bv;
        __syncthreads();

#pragma unroll
        for (int k = 0; k < 8; k++) {
            float a[8], b[8];
            float4 a0 = *reinterpret_cast<const float4*>(&As[k][ty * 8]);
            float4 a1 = *reinterpret_cast<const float4*>(&As[k][ty * 8 + 4]);
            float4 b0 = *reinterpret_cast<const float4*>(&Bs[k][tx * 8]);
            float4 b1 = *reinterpret_cast<const float4*>(&Bs[k][tx * 8 + 4]);
            a[0]=a0.x; a[1]=a0.y; a[2]=a0.z; a[3]=a0.w;
            a[4]=a1.x; a[5]=a1.y; a[6]=a1.z; a[7]=a1.w;
            b[0]=b0.x; b[1]=b0.y; b[2]=b0.z; b[3]=b0.w;
            b[4]=b1.x; b[5]=b1.y; b[6]=b1.z; b[7]=b1.w;
#pragma unroll
            for (int i = 0; i < 8; i++)
#pragma unroll
                for (int j = 0; j < 8; j++) acc[i][j] += a[i] * b[j];
        }
        __syncthreads();
    }

    // epilogue
#pragma unroll
    for (int i = 0; i < 8; i++) {
        int row = block_row + ty * 8 + i;
        if (row >= M) continue;
#pragma unroll
        for (int j = 0; j < 8; j++) {
            int col = block_col + tx * 8 + j;
            float v = acc[i][j] + bias[col];
            if (MODE == 1) v = fmaxf(v, 0.f);
            if (MODE == 2) v += res[(size_t)row * N + col];
            C[(size_t)row * N + col] = v;
        }
    }
}

// ---------------------------------------------------------------------------
// Softmax over 16 contiguous values per (row, head)
// ---------------------------------------------------------------------------
__global__ void softmax16_k(float* __restrict__ aw) {
    int t = blockIdx.x * blockDim.x + threadIdx.x;
    if (t >= MROWS * NHEAD) return;
    float* p = aw + (size_t)t * 16;
    float v[16];
    float mx = -1e30f;
#pragma unroll
    for (int i = 0; i < 16; i++) { v[i] = p[i]; mx = fmaxf(mx, v[i]); }
    float s = 0.f;
#pragma unroll
    for (int i = 0; i < 16; i++) { v[i] = __expf(v[i] - mx); s += v[i]; }
    float inv = 1.f / s;
#pragma unroll
    for (int i = 0; i < 16; i++) p[i] = v[i] * inv;
}

// ---------------------------------------------------------------------------
// Deformable sampling: one warp per (b,q,h); lane = head-dim channel.
// x = ref_x * W + off_x - 0.5 ; bilinear with zero padding.
// ---------------------------------------------------------------------------
__global__ __launch_bounds__(256)
void sample_k(const float* __restrict__ v, const float* __restrict__ off,
              const float* __restrict__ aw, const float* __restrict__ ref,
              float* __restrict__ out) {
    int warp = (blockIdx.x * blockDim.x + threadIdx.x) >> 5;
    int lane = threadIdx.x & 31;
    if (warp >= MROWS * NHEAD) return;
    int h   = warp & 7;
    int row = warp >> 3;          // b*L + q
    int b   = row / LTOT;

    const int HS[4] = {100, 50, 25, 13};
    const int ST[4] = {0, 10000, 12500, 13125};

    const float* offp = off + (size_t)row * 256 + h * 32;  // (h,l,p,c) -> h*32+l*8+p*2+c
    const float* awp  = aw  + (size_t)row * 128 + h * 16;
    const float* refp = ref + (size_t)row * NLVL * 2;

    float acc = 0.f;
#pragma unroll
    for (int l = 0; l < 4; l++) {
        const int H = HS[l], W = HS[l], S = ST[l];
        const float fW = (float)W, fH = (float)H;
        float rx = __ldg(refp + l * 2 + 0);
        float ry = __ldg(refp + l * 2 + 1);
        const float* vbase = v + ((size_t)(b * LTOT + S) * NHEAD + h) * DHEAD + lane;
        const int stride = NHEAD * DHEAD;  // 256 floats per spatial position
#pragma unroll
        for (int p = 0; p < 4; p++) {
            float ox = __ldg(offp + l * 8 + p * 2 + 0);
            float oy = __ldg(offp + l * 8 + p * 2 + 1);
            float a  = __ldg(awp + l * 4 + p);
            float x = rx * fW + ox - 0.5f;
            float y = ry * fH + oy - 0.5f;
            float x0f = floorf(x), y0f = floorf(y);
            float lx = x - x0f, ly = y - y0f;
            int x0 = (int)x0f, y0 = (int)y0f;
            float w00 = (1.f - lx) * (1.f - ly) * a;
            float w10 = lx * (1.f - ly) * a;
            float w01 = (1.f - lx) * ly * a;
            float w11 = lx * ly * a;
            bool vx0 = (x0 >= 0) && (x0 < W);
            bool vx1 = (x0 + 1 >= 0) && (x0 + 1 < W);
            bool vy0 = (y0 >= 0) && (y0 < H);
            bool vy1 = (y0 + 1 >= 0) && (y0 + 1 < H);
            if (vy0 && vx0) acc += w00 * __ldg(vbase + (size_t)(y0 * W + x0) * stride);
            if (vy0 && vx1) acc += w10 * __ldg(vbase + (size_t)(y0 * W + x0 + 1) * stride);
            if (vy1 && vx0) acc += w01 * __ldg(vbase + (size_t)((y0 + 1) * W + x0) * stride);
            if (vy1 && vx1) acc += w11 * __ldg(vbase + (size_t)((y0 + 1) * W + x0 + 1) * stride);
        }
    }
    out[(size_t)row * DMODEL + h * DHEAD + lane] = acc;
}

// ---------------------------------------------------------------------------
// LayerNorm over 256 (one block of 256 threads per row)
// ---------------------------------------------------------------------------
__global__ __launch_bounds__(256)
void ln_k(const float* __restrict__ in, const float* __restrict__ g,
          const float* __restrict__ b, float* __restrict__ out) {
    int row = blockIdx.x;
    int t = threadIdx.x;
    float v = in[(size_t)row * DMODEL + t];
    float s = v, s2 = v * v;
#pragma unroll
    for (int o = 16; o > 0; o >>= 1) {
        s  += __shfl_xor_sync(0xffffffff, s,  o);
        s2 += __shfl_xor_sync(0xffffffff, s2, o);
    }
    __shared__ float sh[8], sh2[8];
    int wid = t >> 5, lane = t & 31;
    if (lane == 0) { sh[wid] = s; sh2[wid] = s2; }
    __syncthreads();
    float ts = 0.f, ts2 = 0.f;
#pragma unroll
    for (int i = 0; i < 8; i++) { ts += sh[i]; ts2 += sh2[i]; }
    float mu = ts * (1.f / DMODEL);
    float var = ts2 * (1.f / DMODEL) - mu * mu;
    float inv = rsqrtf(var + 1e-5f);
    out[(size_t)row * DMODEL + t] = (v - mu) * inv * g[t] + b[t];
}

// ---------------------------------------------------------------------------
// Launch
// ---------------------------------------------------------------------------
extern "C" void kernel_launch(void* const* d_in, const int* in_sizes, int n_in,
                              void* d_out, int out_size) {
    const float* src   = (const float*)d_in[0];
    const float* pos   = (const float*)d_in[1];
    const float* ref   = (const float*)d_in[2];
    // d_in[3]=spatial_shapes, d_in[4]=level_start_index (hardcoded)
    const float* Woff  = (const float*)d_in[5];
    const float* boff  = (const float*)d_in[6];
    const float* Wattn = (const float*)d_in[7];
    const float* battn = (const float*)d_in[8];
    const float* Wval  = (const float*)d_in[9];
    const float* bval  = (const float*)d_in[10];
    const float* Wout  = (const float*)d_in[11];
    const float* bout  = (const float*)d_in[12];
    const float* lsg   = (const float*)d_in[13];
    const float* lsb   = (const float*)d_in[14];
    const float* W1    = (const float*)d_in[15];
    const float* b1    = (const float*)d_in[16];
    const float* W2    = (const float*)d_in[17];
    const float* b2    = (const float*)d_in[18];
    const float* lfg   = (const float*)d_in[19];
    const float* lfb   = (const float*)d_in[20];
    float* out = (float*)d_out;

    float *q, *v, *off, *aw, *samp, *tmp, *x, *h1;
    cudaGetSymbolAddress((void**)&q,    g_q);
    cudaGetSymbolAddress((void**)&v,    g_v);
    cudaGetSymbolAddress((void**)&off,  g_off);
    cudaGetSymbolAddress((void**)&aw,   g_aw);
    cudaGetSymbolAddress((void**)&samp, g_samp);
    cudaGetSymbolAddress((void**)&tmp,  g_tmp);
    cudaGetSymbolAddress((void**)&x,    g_x);
    cudaGetSymbolAddress((void**)&h1,   g_h1);

    const int M = MROWS;
    const int mblk = (M + 127) / 128;   // 416

    // 1. q = src + pos
    {
        int n4 = M * DMODEL / 4;
        add_k<<<(n4 + 255) / 256, 256>>>((const float4*)src, (const float4*)pos,
                                         (float4*)q, n4);
    }
    // 2. v = src @ Wval + bval
    sgemm_k<0><<<dim3(2, mblk), 256>>>(src, Wval, bval, nullptr, v, M, 256, 256);
    // 3. off = q @ Woff + boff
    sgemm_k<0><<<dim3(2, mblk), 256>>>(q, Woff, boff, nullptr, off, M, 256, 256);
    // 4. aw logits = q @ Wattn + battn
    sgemm_k<0><<<dim3(1, mblk), 256>>>(q, Wattn, battn, nullptr, aw, M, 128, 256);
    // 5. softmax over 16 per (row, head)
    softmax16_k<<<(M * NHEAD + 255) / 256, 256>>>(aw);
    // 6. deformable sampling
    sample_k<<<(M * NHEAD) / 8, 256>>>(v, off, aw, ref, samp);
    // 7. tmp = samp @ Wout + bout + src
    sgemm_k<2><<<dim3(2, mblk), 256>>>(samp, Wout, bout, src, tmp, M, 256, 256);
    // 8. x = LN(tmp)
    ln_k<<<M, 256>>>(tmp, lsg, lsb, x);
    // 9. h1 = relu(x @ W1 + b1)
    sgemm_k<1><<<dim3(8, mblk), 256>>>(x, W1, b1, nullptr, h1, M, 1024, 256);
    // 10. tmp = h1 @ W2 + b2 + x
    sgemm_k<2><<<dim3(2, mblk), 256>>>(h1, W2, b2, x, tmp, M, 256, 1024);
    // 11. out = LN(tmp)
    ln_k<<<M, 256>>>(tmp, lfg, lfb, out);
}

// round 4
// speedup vs baseline: 1.6872x; 1.6872x over previous
#include <cuda_runtime.h>
#include <cstdint>

// ---------------------------------------------------------------------------
// Problem constants
// ---------------------------------------------------------------------------
#define BATCH 4
#define LTOT  13294
#define MROWS (BATCH * LTOT)   // 53176
#define DMODEL 256
#define DFFN   1024
#define NHEAD  8
#define NLVL   4
#define NPTS   4
#define DHEAD  32

// ---------------------------------------------------------------------------
// Scratch (device globals; no runtime allocation allowed)
// ---------------------------------------------------------------------------
__device__ float g_q   [MROWS * DMODEL];
__device__ float g_v   [MROWS * DMODEL];
__device__ float g_off [MROWS * DMODEL];
__device__ float g_aw  [MROWS * 128];
__device__ float g_samp[MROWS * DMODEL];
__device__ float g_tmp [MROWS * DMODEL];
__device__ float g_x   [MROWS * DMODEL];
__device__ float g_h1  [MROWS * DFFN];
// transposed weights [N, K]
__device__ float g_wt_val [DMODEL * DMODEL];
__device__ float g_wt_off [DMODEL * DMODEL];
__device__ float g_wt_attn[128 * DMODEL];
__device__ float g_wt_out [DMODEL * DMODEL];
__device__ float g_wt_1   [DFFN * DMODEL];
__device__ float g_wt_2   [DMODEL * DFFN];

// ---------------------------------------------------------------------------
// Helpers
// ---------------------------------------------------------------------------
__device__ __forceinline__ uint32_t f2tf32(float f) {
    uint32_t r;
    asm("cvt.rna.tf32.f32 %0, %1;" : "=r"(r) : "f"(f));
    return r;
}

__device__ __forceinline__ void mma_16n8k8(float* d, const uint32_t* a, const uint32_t* b) {
    asm volatile(
        "mma.sync.aligned.m16n8k8.row.col.f32.tf32.tf32.f32 "
        "{%0,%1,%2,%3}, {%4,%5,%6,%7}, {%8,%9}, {%0,%1,%2,%3};"
        : "+f"(d[0]), "+f"(d[1]), "+f"(d[2]), "+f"(d[3])
        : "r"(a[0]), "r"(a[1]), "r"(a[2]), "r"(a[3]), "r"(b[0]), "r"(b[1]));
}

// ---------------------------------------------------------------------------
// tf32 mma.sync GEMM: C[M,N] = A[M,K] @ Wt[N,K]^T + bias (+relu | +res)
// 128x128 CTA tile, BK=32 double-buffered, 8 warps of 32x64, m16n8k8 tiles.
// MODE: 0 = bias, 1 = bias+relu, 2 = bias+residual
// Requires N % 128 == 0, K % 32 == 0.
// ---------------------------------------------------------------------------
#define LDSS 36                      // padded smem row stride (floats)
#define TILE_F (128 * LDSS)          // floats per tile buffer
#define GEMM_SMEM (4 * TILE_F * 4)   // A0,A1,B0,B1 -> 73728 bytes

template <int MODE>
__global__ __launch_bounds__(256)
void gemm_mma(const float* __restrict__ A, const float* __restrict__ Wt,
              const float* __restrict__ bias, const float* __restrict__ res,
              float* __restrict__ C, int M, int N, int K) {
    extern __shared__ float smem[];
    float* sA[2] = {smem, smem + TILE_F};
    float* sB[2] = {smem + 2 * TILE_F, smem + 3 * TILE_F};

    const int tid  = threadIdx.x;
    const int wid  = tid >> 5;
    const int lane = tid & 31;
    const int g    = lane >> 2;      // groupID 0..7
    const int tig  = lane & 3;       // thread-in-group 0..3
    const int wm   = wid >> 1;       // 0..3 (32-row slab)
    const int wn   = wid & 1;        // 0..1 (64-col slab)
    const int brow = blockIdx.y * 128;
    const int bcol = blockIdx.x * 128;
    const int NC   = K >> 5;

    // per-thread tile-load coords: 4 float4 per matrix per chunk
    const int lrow[4] = {(tid + 0) >> 3, (tid + 256) >> 3, (tid + 512) >> 3, (tid + 768) >> 3};
    const int lc4 = tid & 7;

    float acc[2][8][4];
#pragma unroll
    for (int i = 0; i < 2; i++)
#pragma unroll
        for (int j = 0; j < 8; j++)
#pragma unroll
            for (int t = 0; t < 4; t++) acc[i][j][t] = 0.f;

    auto g_load = [&](int ck, float4* pa, float4* pb) {
        const int k0 = ck << 5;
#pragma unroll
        for (int i = 0; i < 4; i++) {
            int row = lrow[i];
            if (brow + row < M)
                pa[i] = *reinterpret_cast<const float4*>(&A[(size_t)(brow + row) * K + k0 + lc4 * 4]);
            else
                pa[i] = make_float4(0.f, 0.f, 0.f, 0.f);
            pb[i] = *reinterpret_cast<const float4*>(&Wt[(size_t)(bcol + row) * K + k0 + lc4 * 4]);
        }
    };
    auto s_store = [&](int b, const float4* pa, const float4* pb) {
#pragma unroll
        for (int i = 0; i < 4; i++) {
            uint32_t* da = reinterpret_cast<uint32_t*>(&sA[b][lrow[i] * LDSS + lc4 * 4]);
            da[0] = f2tf32(pa[i].x); da[1] = f2tf32(pa[i].y);
            da[2] = f2tf32(pa[i].z); da[3] = f2tf32(pa[i].w);
            uint32_t* db = reinterpret_cast<uint32_t*>(&sB[b][lrow[i] * LDSS + lc4 * 4]);
            db[0] = f2tf32(pb[i].x); db[1] = f2tf32(pb[i].y);
            db[2] = f2tf32(pb[i].z); db[3] = f2tf32(pb[i].w);
        }
    };

    {
        float4 pa[4], pb[4];
        g_load(0, pa, pb);
        s_store(0, pa, pb);
    }
    __syncthreads();

    for (int c = 0; c < NC; ++c) {
        const int b = c & 1;
        float4 pa[4], pb[4];
        if (c + 1 < NC) g_load(c + 1, pa, pb);

        const uint32_t* bufA = reinterpret_cast<const uint32_t*>(sA[b]);
        const uint32_t* bufB = reinterpret_cast<const uint32_t*>(sB[b]);
#pragma unroll
        for (int s = 0; s < 4; s++) {
            const int k = s * 8;
            uint32_t afr[2][4];
#pragma unroll
            for (int i = 0; i < 2; i++) {
                int r = wm * 32 + i * 16 + g;
                afr[i][0] = bufA[(r + 0) * LDSS + k + tig];
                afr[i][1] = bufA[(r + 8) * LDSS + k + tig];
                afr[i][2] = bufA[(r + 0) * LDSS + k + tig + 4];
                afr[i][3] = bufA[(r + 8) * LDSS + k + tig + 4];
            }
#pragma unroll
            for (int j = 0; j < 8; j++) {
                int n = wn * 64 + j * 8 + g;
                uint32_t bfr[2];
                bfr[0] = bufB[n * LDSS + k + tig];
                bfr[1] = bufB[n * LDSS + k + tig + 4];
                mma_16n8k8(acc[0][j], afr[0], bfr);
                mma_16n8k8(acc[1][j], afr[1], bfr);
            }
        }
        if (c + 1 < NC) s_store((c + 1) & 1, pa, pb);
        __syncthreads();
    }

    // epilogue: float2 stores, fused bias (+relu | +residual)
#pragma unroll
    for (int i = 0; i < 2; i++) {
        int r0 = brow + wm * 32 + i * 16 + g;
#pragma unroll
        for (int j = 0; j < 8; j++) {
            int col = bcol + wn * 64 + j * 8 + 2 * tig;
            float b0 = __ldg(&bias[col]);
            float b1 = __ldg(&bias[col + 1]);
            if (r0 < M) {
                float v0 = acc[i][j][0] + b0;
                float v1 = acc[i][j][1] + b1;
                if (MODE == 1) { v0 = fmaxf(v0, 0.f); v1 = fmaxf(v1, 0.f); }
                if (MODE == 2) {
                    const float2 rr = *reinterpret_cast<const float2*>(&res[(size_t)r0 * N + col]);
                    v0 += rr.x; v1 += rr.y;
                }
                *reinterpret_cast<float2*>(&C[(size_t)r0 * N + col]) = make_float2(v0, v1);
            }
            int r1 = r0 + 8;
            if (r1 < M) {
                float v0 = acc[i][j][2] + b0;
                float v1 = acc[i][j][3] + b1;
                if (MODE == 1) { v0 = fmaxf(v0, 0.f); v1 = fmaxf(v1, 0.f); }
                if (MODE == 2) {
                    const float2 rr = *reinterpret_cast<const float2*>(&res[(size_t)r1 * N + col]);
                    v0 += rr.x; v1 += rr.y;
                }
                *reinterpret_cast<float2*>(&C[(size_t)r1 * N + col]) = make_float2(v0, v1);
            }
        }
    }
}

// ---------------------------------------------------------------------------
// Weight transpose: Wt[n*K+k] = W[k*N+n]
// ---------------------------------------------------------------------------
__global__ void transpose_k(const float* __restrict__ W, float* __restrict__ Wt,
                            int K, int N) {
    __shared__ float t[32][33];
    int k0 = blockIdx.y * 32, n0 = blockIdx.x * 32;
    int x = threadIdx.x, y = threadIdx.y;   // 32 x 8
#pragma unroll
    for (int i = 0; i < 32; i += 8)
        t[y + i][x] = W[(size_t)(k0 + y + i) * N + n0 + x];
    __syncthreads();
#pragma unroll
    for (int i = 0; i < 32; i += 8)
        Wt[(size_t)(n0 + y + i) * K + k0 + x] = t[x][y + i];
}

// ---------------------------------------------------------------------------
// Elementwise add
// ---------------------------------------------------------------------------
__global__ void add_k(const float4* __restrict__ a, const float4* __restrict__ b,
                      float4* __restrict__ c, int n4) {
    int i = blockIdx.x * blockDim.x + threadIdx.x;
    if (i >= n4) return;
    float4 x = a[i], y = b[i];
    c[i] = make_float4(x.x + y.x, x.y + y.y, x.z + y.z, x.w + y.w);
}

// ---------------------------------------------------------------------------
// Softmax over 16 contiguous values per (row, head)
// ---------------------------------------------------------------------------
__global__ void softmax16_k(float* __restrict__ aw) {
    int t = blockIdx.x * blockDim.x + threadIdx.x;
    if (t >= MROWS * NHEAD) return;
    float* p = aw + (size_t)t * 16;
    float v[16];
    float mx = -1e30f;
#pragma unroll
    for (int i = 0; i < 16; i++) { v[i] = p[i]; mx = fmaxf(mx, v[i]); }
    float s = 0.f;
#pragma unroll
    for (int i = 0; i < 16; i++) { v[i] = __expf(v[i] - mx); s += v[i]; }
    float inv = 1.f / s;
#pragma unroll
    for (int i = 0; i < 16; i++) p[i] = v[i] * inv;
}

// ---------------------------------------------------------------------------
// Deformable sampling: one warp per (b,q,h); lane = head-dim channel.
// ---------------------------------------------------------------------------
__global__ __launch_bounds__(256)
void sample_k(const float* __restrict__ v, const float* __restrict__ off,
              const float* __restrict__ aw, const float* __restrict__ ref,
              float* __restrict__ out) {
    int warp = (blockIdx.x * blockDim.x + threadIdx.x) >> 5;
    int lane = threadIdx.x & 31;
    if (warp >= MROWS * NHEAD) return;
    int h   = warp & 7;
    int row = warp >> 3;
    int b   = row / LTOT;

    const int HS[4] = {100, 50, 25, 13};
    const int ST[4] = {0, 10000, 12500, 13125};

    const float* offp = off + (size_t)row * 256 + h * 32;
    const float* awp  = aw  + (size_t)row * 128 + h * 16;
    const float* refp = ref + (size_t)row * NLVL * 2;

    float acc = 0.f;
#pragma unroll
    for (int l = 0; l < 4; l++) {
        const int H = HS[l], W = HS[l], S = ST[l];
        const float fW = (float)W, fH = (float)H;
        float rx = __ldg(refp + l * 2 + 0);
        float ry = __ldg(refp + l * 2 + 1);
        const float* vbase = v + ((size_t)(b * LTOT + S) * NHEAD + h) * DHEAD + lane;
        const int stride = NHEAD * DHEAD;
#pragma unroll
        for (int p = 0; p < 4; p++) {
            float ox = __ldg(offp + l * 8 + p * 2 + 0);
            float oy = __ldg(offp + l * 8 + p * 2 + 1);
            float a  = __ldg(awp + l * 4 + p);
            float x = rx * fW + ox - 0.5f;
            float y = ry * fH + oy - 0.5f;
            float x0f = floorf(x), y0f = floorf(y);
            float lx = x - x0f, ly = y - y0f;
            int x0 = (int)x0f, y0 = (int)y0f;
            float w00 = (1.f - lx) * (1.f - ly) * a;
            float w10 = lx * (1.f - ly) * a;
            float w01 = (1.f - lx) * ly * a;
            float w11 = lx * ly * a;
            bool vx0 = (x0 >= 0) && (x0 < W);
            bool vx1 = (x0 + 1 >= 0) && (x0 + 1 < W);
            bool vy0 = (y0 >= 0) && (y0 < H);
            bool vy1 = (y0 + 1 >= 0) && (y0 + 1 < H);
            if (vy0 && vx0) acc += w00 * __ldg(vbase + (size_t)(y0 * W + x0) * stride);
            if (vy0 && vx1) acc += w10 * __ldg(vbase + (size_t)(y0 * W + x0 + 1) * stride);
            if (vy1 && vx0) acc += w01 * __ldg(vbase + (size_t)((y0 + 1) * W + x0) * stride);
            if (vy1 && vx1) acc += w11 * __ldg(vbase + (size_t)((y0 + 1) * W + x0 + 1) * stride);
        }
    }
    out[(size_t)row * DMODEL + h * DHEAD + lane] = acc;
}

// ---------------------------------------------------------------------------
// LayerNorm over 256
// ---------------------------------------------------------------------------
__global__ __launch_bounds__(256)
void ln_k(const float* __restrict__ in, const float* __restrict__ g,
          const float* __restrict__ b, float* __restrict__ out) {
    int row = blockIdx.x;
    int t = threadIdx.x;
    float v = in[(size_t)row * DMODEL + t];
    float s = v, s2 = v * v;
#pragma unroll
    for (int o = 16; o > 0; o >>= 1) {
        s  += __shfl_xor_sync(0xffffffff, s,  o);
        s2 += __shfl_xor_sync(0xffffffff, s2, o);
    }
    __shared__ float sh[8], sh2[8];
    int wid = t >> 5, lane = t & 31;
    if (lane == 0) { sh[wid] = s; sh2[wid] = s2; }
    __syncthreads();
    float ts = 0.f, ts2 = 0.f;
#pragma unroll
    for (int i = 0; i < 8; i++) { ts += sh[i]; ts2 += sh2[i]; }
    float mu = ts * (1.f / DMODEL);
    float var = ts2 * (1.f / DMODEL) - mu * mu;
    float inv = rsqrtf(var + 1e-5f);
    out[(size_t)row * DMODEL + t] = (v - mu) * inv * g[t] + b[t];
}

// ---------------------------------------------------------------------------
// Launch
// ---------------------------------------------------------------------------
extern "C" void kernel_launch(void* const* d_in, const int* in_sizes, int n_in,
                              void* d_out, int out_size) {
    const float* src   = (const float*)d_in[0];
    const float* pos   = (const float*)d_in[1];
    const float* ref   = (const float*)d_in[2];
    const float* Woff  = (const float*)d_in[5];
    const float* boff  = (const float*)d_in[6];
    const float* Wattn = (const float*)d_in[7];
    const float* battn = (const float*)d_in[8];
    const float* Wval  = (const float*)d_in[9];
    const float* bval  = (const float*)d_in[10];
    const float* Wout  = (const float*)d_in[11];
    const float* bout  = (const float*)d_in[12];
    const float* lsg   = (const float*)d_in[13];
    const float* lsb   = (const float*)d_in[14];
    const float* W1    = (const float*)d_in[15];
    const float* b1    = (const float*)d_in[16];
    const float* W2    = (const float*)d_in[17];
    const float* b2    = (const float*)d_in[18];
    const float* lfg   = (const float*)d_in[19];
    const float* lfb   = (const float*)d_in[20];
    float* out = (float*)d_out;

    float *q, *v, *off, *aw, *samp, *tmp, *x, *h1;
    float *wtv, *wto, *wta, *wtO, *wt1, *wt2;
    cudaGetSymbolAddress((void**)&q,    g_q);
    cudaGetSymbolAddress((void**)&v,    g_v);
    cudaGetSymbolAddress((void**)&off,  g_off);
    cudaGetSymbolAddress((void**)&aw,   g_aw);
    cudaGetSymbolAddress((void**)&samp, g_samp);
    cudaGetSymbolAddress((void**)&tmp,  g_tmp);
    cudaGetSymbolAddress((void**)&x,    g_x);
    cudaGetSymbolAddress((void**)&h1,   g_h1);
    cudaGetSymbolAddress((void**)&wtv,  g_wt_val);
    cudaGetSymbolAddress((void**)&wto,  g_wt_off);
    cudaGetSymbolAddress((void**)&wta,  g_wt_attn);
    cudaGetSymbolAddress((void**)&wtO,  g_wt_out);
    cudaGetSymbolAddress((void**)&wt1,  g_wt_1);
    cudaGetSymbolAddress((void**)&wt2,  g_wt_2);

    cudaFuncSetAttribute(gemm_mma<0>, cudaFuncAttributeMaxDynamicSharedMemorySize, GEMM_SMEM);
    cudaFuncSetAttribute(gemm_mma<1>, cudaFuncAttributeMaxDynamicSharedMemorySize, GEMM_SMEM);
    cudaFuncSetAttribute(gemm_mma<2>, cudaFuncAttributeMaxDynamicSharedMemorySize, GEMM_SMEM);

    const int M = MROWS;
    const int mblk = (M + 127) / 128;   // 416
    dim3 tb(32, 8);

    // weight transposes (tiny)
    transpose_k<<<dim3(8, 8),  tb>>>(Wval,  wtv, 256, 256);
    transpose_k<<<dim3(8, 8),  tb>>>(Woff,  wto, 256, 256);
    transpose_k<<<dim3(4, 8),  tb>>>(Wattn, wta, 256, 128);
    transpose_k<<<dim3(8, 8),  tb>>>(Wout,  wtO, 256, 256);
    transpose_k<<<dim3(32, 8), tb>>>(W1,    wt1, 256, 1024);
    transpose_k<<<dim3(8, 32), tb>>>(W2,    wt2, 1024, 256);

    // 1. q = src + pos
    {
        int n4 = M * DMODEL / 4;
        add_k<<<(n4 + 255) / 256, 256>>>((const float4*)src, (const float4*)pos,
                                         (float4*)q, n4);
    }
    // 2. v = src @ Wval + bval
    gemm_mma<0><<<dim3(2, mblk), 256, GEMM_SMEM>>>(src, wtv, bval, nullptr, v, M, 256, 256);
    // 3. off = q @ Woff + boff
    gemm_mma<0><<<dim3(2, mblk), 256, GEMM_SMEM>>>(q, wto, boff, nullptr, off, M, 256, 256);
    // 4. aw logits = q @ Wattn + battn
    gemm_mma<0><<<dim3(1, mblk), 256, GEMM_SMEM>>>(q, wta, battn, nullptr, aw, M, 128, 256);
    // 5. softmax
    softmax16_k<<<(M * NHEAD + 255) / 256, 256>>>(aw);
    // 6. deformable sampling
    sample_k<<<(M * NHEAD) / 8, 256>>>(v, off, aw, ref, samp);
    // 7. tmp = samp @ Wout + bout + src
    gemm_mma<2><<<dim3(2, mblk), 256, GEMM_SMEM>>>(samp, wtO, bout, src, tmp, M, 256, 256);
    // 8. x = LN(tmp)
    ln_k<<<M, 256>>>(tmp, lsg, lsb, x);
    // 9. h1 = relu(x @ W1 + b1)
    gemm_mma<1><<<dim3(8, mblk), 256, GEMM_SMEM>>>(x, wt1, b1, nullptr, h1, M, 1024, 256);
    // 10. tmp = h1 @ W2 + b2 + x
    gemm_mma<2><<<dim3(2, mblk), 256, GEMM_SMEM>>>(h1, wt2, b2, x, tmp, M, 256, 1024);
    // 11. out = LN(tmp)
    ln_k<<<M, 256>>>(tmp, lfg, lfb, out);
}

// round 5
// speedup vs baseline: 2.4313x; 1.4410x over previous
#include <cuda_runtime.h>
#include <cstdint>

// ---------------------------------------------------------------------------
// Problem constants
// ---------------------------------------------------------------------------
#define BATCH 4
#define LTOT  13294
#define MROWS (BATCH * LTOT)   // 53176
#define DMODEL 256
#define DFFN   1024
#define NHEAD  8
#define NLVL   4
#define NPTS   4
#define DHEAD  32

// ---------------------------------------------------------------------------
// Scratch (device globals; no runtime allocation allowed)
// ---------------------------------------------------------------------------
__device__ float g_q   [MROWS * DMODEL];
__device__ float g_v   [MROWS * DMODEL];
__device__ float g_off [MROWS * DMODEL];
__device__ float g_aw  [MROWS * 128];
__device__ float g_samp[MROWS * DMODEL];
__device__ float g_tmp [MROWS * DMODEL];
__device__ float g_x   [MROWS * DMODEL];
__device__ float g_h1  [MROWS * DFFN];
// transposed weights [N, K] (tf32-rounded)
__device__ float g_wt_val [DMODEL * DMODEL];
__device__ float g_wt_off [DMODEL * DMODEL];
__device__ float g_wt_attn[128 * DMODEL];
__device__ float g_wt_out [DMODEL * DMODEL];
__device__ float g_wt_1   [DFFN * DMODEL];
__device__ float g_wt_2   [DMODEL * DFFN];

// ---------------------------------------------------------------------------
// Helpers
// ---------------------------------------------------------------------------
__device__ __forceinline__ uint32_t f2tf32(float f) {
    uint32_t r;
    asm("cvt.rna.tf32.f32 %0, %1;" : "=r"(r) : "f"(f));
    return r;
}

__device__ __forceinline__ void mma_16n8k8(float* d, const uint32_t* a, const uint32_t* b) {
    asm volatile(
        "mma.sync.aligned.m16n8k8.row.col.f32.tf32.tf32.f32 "
        "{%0,%1,%2,%3}, {%4,%5,%6,%7}, {%8,%9}, {%0,%1,%2,%3};"
        : "+f"(d[0]), "+f"(d[1]), "+f"(d[2]), "+f"(d[3])
        : "r"(a[0]), "r"(a[1]), "r"(a[2]), "r"(a[3]), "r"(b[0]), "r"(b[1]));
}

#define CP_ASYNC16(dst, src, nbytes) \
    asm volatile("cp.async.cg.shared.global [%0], [%1], 16, %2;" \
        :: "r"(dst), "l"(src), "r"(nbytes))
#define CP_COMMIT() asm volatile("cp.async.commit_group;")
#define CP_WAIT1()  asm volatile("cp.async.wait_group 1;")
#define CP_WAIT0()  asm volatile("cp.async.wait_group 0;")

// ---------------------------------------------------------------------------
// tf32 mma.sync GEMM with cp.async 2-stage pipeline.
// C[M,N] = A[M,K] @ Wt[N,K]^T + bias (+relu | +res)
// 128x128 CTA tile, BK=32, 8 warps of 32x64, m16n8k8.
// Wt must be pre-rounded to tf32. A is rounded (RNA) at fragment load.
// MODE: 0 = bias, 1 = bias+relu, 2 = bias+residual
// ---------------------------------------------------------------------------
#define LDSS 36                      // padded smem row stride (floats)
#define TILE_F (128 * LDSS)          // floats per tile buffer
#define GEMM_SMEM (4 * TILE_F * 4)   // A0,A1,B0,B1 -> 73728 bytes

template <int MODE>
__global__ __launch_bounds__(256)
void gemm_mma(const float* __restrict__ A, const float* __restrict__ Wt,
              const float* __restrict__ bias, const float* __restrict__ res,
              float* __restrict__ C, int M, int N, int K) {
    extern __shared__ float smem[];
    float* sA[2] = {smem, smem + TILE_F};
    float* sB[2] = {smem + 2 * TILE_F, smem + 3 * TILE_F};

    const int tid  = threadIdx.x;
    const int wid  = tid >> 5;
    const int lane = tid & 31;
    const int g    = lane >> 2;      // groupID 0..7
    const int tig  = lane & 3;       // thread-in-group 0..3
    const int wm   = wid >> 1;       // 0..3 (32-row slab)
    const int wn   = wid & 1;        // 0..1 (64-col slab)
    const int brow = blockIdx.y * 128;
    const int bcol = blockIdx.x * 128;
    const int NC   = K >> 5;

    const int lrow[4] = {(tid + 0) >> 3, (tid + 256) >> 3, (tid + 512) >> 3, (tid + 768) >> 3};
    const int lc4 = tid & 7;

    // precompute shared dst addresses
    uint32_t dA[2][4], dB[2][4];
#pragma unroll
    for (int b = 0; b < 2; b++)
#pragma unroll
        for (int i = 0; i < 4; i++) {
            dA[b][i] = (uint32_t)__cvta_generic_to_shared(&sA[b][lrow[i] * LDSS + lc4 * 4]);
            dB[b][i] = (uint32_t)__cvta_generic_to_shared(&sB[b][lrow[i] * LDSS + lc4 * 4]);
        }

    float acc[2][8][4];
#pragma unroll
    for (int i = 0; i < 2; i++)
#pragma unroll
        for (int j = 0; j < 8; j++)
#pragma unroll
            for (int t = 0; t < 4; t++) acc[i][j][t] = 0.f;

    auto issue = [&](int ck) {
        const int b = ck & 1;
        const int k0 = ck << 5;
#pragma unroll
        for (int i = 0; i < 4; i++) {
            int row = lrow[i];
            CP_ASYNC16(dA[b][i], &A[(size_t)(brow + row) * K + k0 + lc4 * 4],
                       (brow + row < M) ? 16 : 0);
            CP_ASYNC16(dB[b][i], &Wt[(size_t)(bcol + row) * K + k0 + lc4 * 4], 16);
        }
        CP_COMMIT();
    };

    issue(0);
    for (int c = 0; c < NC; ++c) {
        const int b = c & 1;
        if (c + 1 < NC) { issue(c + 1); CP_WAIT1(); }
        else            { CP_WAIT0(); }
        __syncthreads();

        const uint32_t* bufA = reinterpret_cast<const uint32_t*>(sA[b]);
        const uint32_t* bufB = reinterpret_cast<const uint32_t*>(sB[b]);
#pragma unroll
        for (int s = 0; s < 4; s++) {
            const int k = s * 8;
            uint32_t afr[2][4];
#pragma unroll
            for (int i = 0; i < 2; i++) {
                int r = wm * 32 + i * 16 + g;
                afr[i][0] = f2tf32(__uint_as_float(bufA[(r + 0) * LDSS + k + tig]));
                afr[i][1] = f2tf32(__uint_as_float(bufA[(r + 8) * LDSS + k + tig]));
                afr[i][2] = f2tf32(__uint_as_float(bufA[(r + 0) * LDSS + k + tig + 4]));
                afr[i][3] = f2tf32(__uint_as_float(bufA[(r + 8) * LDSS + k + tig + 4]));
            }
#pragma unroll
            for (int j = 0; j < 8; j++) {
                int n = wn * 64 + j * 8 + g;
                uint32_t bfr[2];
                bfr[0] = bufB[n * LDSS + k + tig];
                bfr[1] = bufB[n * LDSS + k + tig + 4];
                mma_16n8k8(acc[0][j], afr[0], bfr);
                mma_16n8k8(acc[1][j], afr[1], bfr);
            }
        }
        __syncthreads();
    }

    // epilogue: float2 stores, fused bias (+relu | +residual)
#pragma unroll
    for (int i = 0; i < 2; i++) {
        int r0 = brow + wm * 32 + i * 16 + g;
#pragma unroll
        for (int j = 0; j < 8; j++) {
            int col = bcol + wn * 64 + j * 8 + 2 * tig;
            float b0 = __ldg(&bias[col]);
            float b1 = __ldg(&bias[col + 1]);
            if (r0 < M) {
                float v0 = acc[i][j][0] + b0;
                float v1 = acc[i][j][1] + b1;
                if (MODE == 1) { v0 = fmaxf(v0, 0.f); v1 = fmaxf(v1, 0.f); }
                if (MODE == 2) {
                    const float2 rr = *reinterpret_cast<const float2*>(&res[(size_t)r0 * N + col]);
                    v0 += rr.x; v1 += rr.y;
                }
                *reinterpret_cast<float2*>(&C[(size_t)r0 * N + col]) = make_float2(v0, v1);
            }
            int r1 = r0 + 8;
            if (r1 < M) {
                float v0 = acc[i][j][2] + b0;
                float v1 = acc[i][j][3] + b1;
                if (MODE == 1) { v0 = fmaxf(v0, 0.f); v1 = fmaxf(v1, 0.f); }
                if (MODE == 2) {
                    const float2 rr = *reinterpret_cast<const float2*>(&res[(size_t)r1 * N + col]);
                    v0 += rr.x; v1 += rr.y;
                }
                *reinterpret_cast<float2*>(&C[(size_t)r1 * N + col]) = make_float2(v0, v1);
            }
        }
    }
}

// ---------------------------------------------------------------------------
// Weight transpose + tf32 round: Wt[n*K+k] = tf32(W[k*N+n])
// ---------------------------------------------------------------------------
__global__ void transpose_k(const float* __restrict__ W, float* __restrict__ Wt,
                            int K, int N) {
    __shared__ float t[32][33];
    int k0 = blockIdx.y * 32, n0 = blockIdx.x * 32;
    int x = threadIdx.x, y = threadIdx.y;   // 32 x 8
#pragma unroll
    for (int i = 0; i < 32; i += 8)
        t[y + i][x] = W[(size_t)(k0 + y + i) * N + n0 + x];
    __syncthreads();
#pragma unroll
    for (int i = 0; i < 32; i += 8)
        Wt[(size_t)(n0 + y + i) * K + k0 + x] =
            __uint_as_float(f2tf32(t[x][y + i]));
}

// ---------------------------------------------------------------------------
// Elementwise add
// ---------------------------------------------------------------------------
__global__ void add_k(const float4* __restrict__ a, const float4* __restrict__ b,
                      float4* __restrict__ c, int n4) {
    int i = blockIdx.x * blockDim.x + threadIdx.x;
    if (i >= n4) return;
    float4 x = a[i], y = b[i];
    c[i] = make_float4(x.x + y.x, x.y + y.y, x.z + y.z, x.w + y.w);
}

// ---------------------------------------------------------------------------
// Deformable sampling v2: one warp per (b,q,h); lane = (point p, channel-quad c4).
// Softmax over the 16 (level,point) logits fused in via shuffles.
// All value gathers are 128-bit.
// ---------------------------------------------------------------------------
__global__ __launch_bounds__(256)
void sample_k(const float* __restrict__ v, const float* __restrict__ off,
              const float* __restrict__ logit, const float* __restrict__ ref,
              float* __restrict__ out) {
    int warp = (blockIdx.x * blockDim.x + threadIdx.x) >> 5;
    int lane = threadIdx.x & 31;
    if (warp >= MROWS * NHEAD) return;
    int h   = warp & 7;
    int row = warp >> 3;
    int b   = row / LTOT;
    int p   = lane >> 3;      // point 0..3
    int c4  = lane & 7;       // channel quad 0..7

    const int HS[4] = {100, 50, 25, 13};
    const int ST[4] = {0, 10000, 12500, 13125};

    const float* offp = off   + (size_t)row * 256 + h * 32;
    const float* lgp  = logit + (size_t)row * 128 + h * 16;
    const float* refp = ref   + (size_t)row * 8;

    // fused softmax over 16 logits: lane's p covers 4 of them (one per level)
    float lg[4];
#pragma unroll
    for (int l = 0; l < 4; l++) lg[l] = __ldg(lgp + l * 4 + p);
    float mx = fmaxf(fmaxf(lg[0], lg[1]), fmaxf(lg[2], lg[3]));
    mx = fmaxf(mx, __shfl_xor_sync(0xffffffffu, mx, 8));
    mx = fmaxf(mx, __shfl_xor_sync(0xffffffffu, mx, 16));
    float e[4], s = 0.f;
#pragma unroll
    for (int l = 0; l < 4; l++) { e[l] = __expf(lg[l] - mx); s += e[l]; }
    s += __shfl_xor_sync(0xffffffffu, s, 8);
    s += __shfl_xor_sync(0xffffffffu, s, 16);
    const float inv = 1.f / s;

    float ax = 0.f, ay = 0.f, az = 0.f, aq = 0.f;
#pragma unroll
    for (int l = 0; l < 4; l++) {
        const int H = HS[l], W = HS[l], S = ST[l];
        float rx = __ldg(refp + l * 2 + 0);
        float ry = __ldg(refp + l * 2 + 1);
        float ox = __ldg(offp + l * 8 + p * 2 + 0);
        float oy = __ldg(offp + l * 8 + p * 2 + 1);
        float aww = e[l] * inv;
        float x = rx * (float)W + ox - 0.5f;
        float y = ry * (float)H + oy - 0.5f;
        float x0f = floorf(x), y0f = floorf(y);
        float lx = x - x0f, ly = y - y0f;
        int x0 = (int)x0f, y0 = (int)y0f;
        float w00 = (1.f - lx) * (1.f - ly) * aww;
        float w10 = lx * (1.f - ly) * aww;
        float w01 = (1.f - lx) * ly * aww;
        float w11 = lx * ly * aww;
        bool vx0 = (x0 >= 0) && (x0 < W);
        bool vx1 = (x0 + 1 >= 0) && (x0 + 1 < W);
        bool vy0 = (y0 >= 0) && (y0 < H);
        bool vy1 = (y0 + 1 >= 0) && (y0 + 1 < H);
        // float4 base: element (b, S+idx, h, c4*4)
        const float4* vb = reinterpret_cast<const float4*>(
            v + ((size_t)(b * LTOT + S) * NHEAD + h) * DHEAD) + c4;
        const int str4 = NHEAD * DHEAD / 4;  // 64 float4 per spatial index
        if (vy0 && vx0) {
            float4 t = __ldg(vb + (size_t)(y0 * W + x0) * str4);
            ax += w00 * t.x; ay += w00 * t.y; az += w00 * t.z; aq += w00 * t.w;
        }
        if (vy0 && vx1) {
            float4 t = __ldg(vb + (size_t)(y0 * W + x0 + 1) * str4);
            ax += w10 * t.x; ay += w10 * t.y; az += w10 * t.z; aq += w10 * t.w;
        }
        if (vy1 && vx0) {
            float4 t = __ldg(vb + (size_t)((y0 + 1) * W + x0) * str4);
            ax += w01 * t.x; ay += w01 * t.y; az += w01 * t.z; aq += w01 * t.w;
        }
        if (vy1 && vx1) {
            float4 t = __ldg(vb + (size_t)((y0 + 1) * W + x0 + 1) * str4);
            ax += w11 * t.x; ay += w11 * t.y; az += w11 * t.z; aq += w11 * t.w;
        }
    }
    // reduce over point (lane bits 3,4)
#pragma unroll
    for (int o = 8; o <= 16; o <<= 1) {
        ax += __shfl_xor_sync(0xffffffffu, ax, o);
        ay += __shfl_xor_sync(0xffffffffu, ay, o);
        az += __shfl_xor_sync(0xffffffffu, az, o);
        aq += __shfl_xor_sync(0xffffffffu, aq, o);
    }
    if (p == 0)
        *reinterpret_cast<float4*>(&out[(size_t)row * DMODEL + h * DHEAD + c4 * 4]) =
            make_float4(ax, ay, az, aq);
}

// ---------------------------------------------------------------------------
// LayerNorm over 256
// ---------------------------------------------------------------------------
__global__ __launch_bounds__(256)
void ln_k(const float* __restrict__ in, const float* __restrict__ g,
          const float* __restrict__ b, float* __restrict__ out) {
    int row = blockIdx.x;
    int t = threadIdx.x;
    float v = in[(size_t)row * DMODEL + t];
    float s = v, s2 = v * v;
#pragma unroll
    for (int o = 16; o > 0; o >>= 1) {
        s  += __shfl_xor_sync(0xffffffff, s,  o);
        s2 += __shfl_xor_sync(0xffffffff, s2, o);
    }
    __shared__ float sh[8], sh2[8];
    int wid = t >> 5, lane = t & 31;
    if (lane == 0) { sh[wid] = s; sh2[wid] = s2; }
    __syncthreads();
    float ts = 0.f, ts2 = 0.f;
#pragma unroll
    for (int i = 0; i < 8; i++) { ts += sh[i]; ts2 += sh2[i]; }
    float mu = ts * (1.f / DMODEL);
    float var = ts2 * (1.f / DMODEL) - mu * mu;
    float inv = rsqrtf(var + 1e-5f);
    out[(size_t)row * DMODEL + t] = (v - mu) * inv * g[t] + b[t];
}

// ---------------------------------------------------------------------------
// Launch
// ---------------------------------------------------------------------------
extern "C" void kernel_launch(void* const* d_in, const int* in_sizes, int n_in,
                              void* d_out, int out_size) {
    const float* src   = (const float*)d_in[0];
    const float* pos   = (const float*)d_in[1];
    const float* ref   = (const float*)d_in[2];
    const float* Woff  = (const float*)d_in[5];
    const float* boff  = (const float*)d_in[6];
    const float* Wattn = (const float*)d_in[7];
    const float* battn = (const float*)d_in[8];
    const float* Wval  = (const float*)d_in[9];
    const float* bval  = (const float*)d_in[10];
    const float* Wout  = (const float*)d_in[11];
    const float* bout  = (const float*)d_in[12];
    const float* lsg   = (const float*)d_in[13];
    const float* lsb   = (const float*)d_in[14];
    const float* W1    = (const float*)d_in[15];
    const float* b1    = (const float*)d_in[16];
    const float* W2    = (const float*)d_in[17];
    const float* b2    = (const float*)d_in[18];
    const float* lfg   = (const float*)d_in[19];
    const float* lfb   = (const float*)d_in[20];
    float* out = (float*)d_out;

    float *q, *v, *off, *aw, *samp, *tmp, *x, *h1;
    float *wtv, *wto, *wta, *wtO, *wt1, *wt2;
    cudaGetSymbolAddress((void**)&q,    g_q);
    cudaGetSymbolAddress((void**)&v,    g_v);
    cudaGetSymbolAddress((void**)&off,  g_off);
    cudaGetSymbolAddress((void**)&aw,   g_aw);
    cudaGetSymbolAddress((void**)&samp, g_samp);
    cudaGetSymbolAddress((void**)&tmp,  g_tmp);
    cudaGetSymbolAddress((void**)&x,    g_x);
    cudaGetSymbolAddress((void**)&h1,   g_h1);
    cudaGetSymbolAddress((void**)&wtv,  g_wt_val);
    cudaGetSymbolAddress((void**)&wto,  g_wt_off);
    cudaGetSymbolAddress((void**)&wta,  g_wt_attn);
    cudaGetSymbolAddress((void**)&wtO,  g_wt_out);
    cudaGetSymbolAddress((void**)&wt1,  g_wt_1);
    cudaGetSymbolAddress((void**)&wt2,  g_wt_2);

    cudaFuncSetAttribute(gemm_mma<0>, cudaFuncAttributeMaxDynamicSharedMemorySize, GEMM_SMEM);
    cudaFuncSetAttribute(gemm_mma<1>, cudaFuncAttributeMaxDynamicSharedMemorySize, GEMM_SMEM);
    cudaFuncSetAttribute(gemm_mma<2>, cudaFuncAttributeMaxDynamicSharedMemorySize, GEMM_SMEM);

    const int M = MROWS;
    const int mblk = (M + 127) / 128;   // 416
    dim3 tb(32, 8);

    // weight transposes + tf32 rounding (tiny)
    transpose_k<<<dim3(8, 8),  tb>>>(Wval,  wtv, 256, 256);
    transpose_k<<<dim3(8, 8),  tb>>>(Woff,  wto, 256, 256);
    transpose_k<<<dim3(4, 8),  tb>>>(Wattn, wta, 256, 128);
    transpose_k<<<dim3(8, 8),  tb>>>(Wout,  wtO, 256, 256);
    transpose_k<<<dim3(32, 8), tb>>>(W1,    wt1, 256, 1024);
    transpose_k<<<dim3(8, 32), tb>>>(W2,    wt2, 1024, 256);

    // 1. q = src + pos
    {
        int n4 = M * DMODEL / 4;
        add_k<<<(n4 + 255) / 256, 256>>>((const float4*)src, (const float4*)pos,
                                         (float4*)q, n4);
    }
    // 2. v = src @ Wval + bval
    gemm_mma<0><<<dim3(2, mblk), 256, GEMM_SMEM>>>(src, wtv, bval, nullptr, v, M, 256, 256);
    // 3. off = q @ Woff + boff
    gemm_mma<0><<<dim3(2, mblk), 256, GEMM_SMEM>>>(q, wto, boff, nullptr, off, M, 256, 256);
    // 4. aw logits = q @ Wattn + battn
    gemm_mma<0><<<dim3(1, mblk), 256, GEMM_SMEM>>>(q, wta, battn, nullptr, aw, M, 128, 256);
    // 5+6. deformable sampling with fused softmax
    sample_k<<<(M * NHEAD) / 8, 256>>>(v, off, aw, ref, samp);
    // 7. tmp = samp @ Wout + bout + src
    gemm_mma<2><<<dim3(2, mblk), 256, GEMM_SMEM>>>(samp, wtO, bout, src, tmp, M, 256, 256);
    // 8. x = LN(tmp)
    ln_k<<<M, 256>>>(tmp, lsg, lsb, x);
    // 9. h1 = relu(x @ W1 + b1)
    gemm_mma<1><<<dim3(8, mblk), 256, GEMM_SMEM>>>(x, wt1, b1, nullptr, h1, M, 1024, 256);
    // 10. tmp = h1 @ W2 + b2 + x
    gemm_mma<2><<<dim3(2, mblk), 256, GEMM_SMEM>>>(h1, wt2, b2, x, tmp, M, 256, 1024);
    // 11. out = LN(tmp)
    ln_k<<<M, 256>>>(tmp, lfg, lfb, out);
}

// round 6
// speedup vs baseline: 2.8956x; 1.1910x over previous
#include <cuda_runtime.h>
#include <cstdint>

// ---------------------------------------------------------------------------
// Problem constants
// ---------------------------------------------------------------------------
#define BATCH 4
#define LTOT  13294
#define MROWS (BATCH * LTOT)   // 53176
#define DMODEL 256
#define DFFN   1024
#define NHEAD  8
#define NLVL   4
#define NPTS   4
#define DHEAD  32

// ---------------------------------------------------------------------------
// Scratch (device globals; no runtime allocation allowed)
// ---------------------------------------------------------------------------
__device__ float g_q   [MROWS * DMODEL];
__device__ float g_v   [MROWS * DMODEL];
__device__ float g_oa  [MROWS * 384];     // fused offsets(256) + attn logits(128)
__device__ float g_samp[MROWS * DMODEL];
__device__ float g_tmp [MROWS * DMODEL];
__device__ float g_x   [MROWS * DMODEL];
__device__ float g_h1  [MROWS * DFFN];
// transposed weights [N, K] (tf32-rounded)
__device__ float g_wt_val [DMODEL * DMODEL];
__device__ float g_wt_oa  [384 * DMODEL];
__device__ float g_wt_out [DMODEL * DMODEL];
__device__ float g_wt_1   [DFFN * DMODEL];
__device__ float g_wt_2   [DMODEL * DFFN];
__device__ float g_bias_oa[384];

// ---------------------------------------------------------------------------
// Helpers
// ---------------------------------------------------------------------------
__device__ __forceinline__ uint32_t f2tf32(float f) {
    uint32_t r;
    asm("cvt.rna.tf32.f32 %0, %1;" : "=r"(r) : "f"(f));
    return r;
}

__device__ __forceinline__ void mma_16n8k8(float* d, const uint32_t* a, const uint32_t* b) {
    asm volatile(
        "mma.sync.aligned.m16n8k8.row.col.f32.tf32.tf32.f32 "
        "{%0,%1,%2,%3}, {%4,%5,%6,%7}, {%8,%9}, {%0,%1,%2,%3};"
        : "+f"(d[0]), "+f"(d[1]), "+f"(d[2]), "+f"(d[3])
        : "r"(a[0]), "r"(a[1]), "r"(a[2]), "r"(a[3]), "r"(b[0]), "r"(b[1]));
}

#define CP_ASYNC16(dst, src, nbytes) \
    asm volatile("cp.async.cg.shared.global [%0], [%1], 16, %2;" \
        :: "r"(dst), "l"(src), "r"(nbytes))
#define CP_COMMIT() asm volatile("cp.async.commit_group;")
#define CP_WAIT1()  asm volatile("cp.async.wait_group 1;")
#define CP_WAIT0()  asm volatile("cp.async.wait_group 0;")

// ---------------------------------------------------------------------------
// tf32 mma.sync GEMM, 3-stage cp.async pipeline.
// C[M,N] = A[M,K] @ Wt[N,K]^T + bias (+relu | +res)
// 128x128 CTA tile, BK=32, 8 warps of 32x64, m16n8k8.
// Wt pre-rounded to tf32; A rounded (RNA) at fragment load.
// MODE: 0 = bias, 1 = bias+relu, 2 = bias+residual
// ---------------------------------------------------------------------------
#define LDSS 36                      // padded smem row stride (floats)
#define TILE_F (128 * LDSS)          // floats per tile buffer
#define TILE_BYTES (TILE_F * 4)      // 18432
#define GEMM_SMEM (6 * TILE_BYTES)   // A0..2, B0..2 -> 110592 bytes

template <int MODE>
__global__ __launch_bounds__(256)
void gemm_mma(const float* __restrict__ A, const float* __restrict__ Wt,
              const float* __restrict__ bias, const float* __restrict__ res,
              float* __restrict__ C, int M, int N, int K) {
    extern __shared__ float smem[];
    float* sAbase = smem;                 // 3 tiles
    float* sBbase = smem + 3 * TILE_F;    // 3 tiles

    const int tid  = threadIdx.x;
    const int wid  = tid >> 5;
    const int lane = tid & 31;
    const int g    = lane >> 2;      // groupID 0..7
    const int tig  = lane & 3;       // thread-in-group 0..3
    const int wm   = wid >> 1;       // 0..3 (32-row slab)
    const int wn   = wid & 1;        // 0..1 (64-col slab)
    const int brow = blockIdx.y * 128;
    const int bcol = blockIdx.x * 128;
    const int NC   = K >> 5;

    const int lrow[4] = {(tid + 0) >> 3, (tid + 256) >> 3, (tid + 512) >> 3, (tid + 768) >> 3};
    const int lc4 = tid & 7;

    uint32_t baseA[4], baseB[4];
#pragma unroll
    for (int i = 0; i < 4; i++) {
        baseA[i] = (uint32_t)__cvta_generic_to_shared(&sAbase[lrow[i] * LDSS + lc4 * 4]);
        baseB[i] = (uint32_t)__cvta_generic_to_shared(&sBbase[lrow[i] * LDSS + lc4 * 4]);
    }

    float acc[2][8][4];
#pragma unroll
    for (int i = 0; i < 2; i++)
#pragma unroll
        for (int j = 0; j < 8; j++)
#pragma unroll
            for (int t = 0; t < 4; t++) acc[i][j][t] = 0.f;

    auto issue = [&](int ck) {
        const uint32_t boff = (uint32_t)(ck % 3) * TILE_BYTES;
        const int k0 = ck << 5;
#pragma unroll
        for (int i = 0; i < 4; i++) {
            int row = lrow[i];
            CP_ASYNC16(baseA[i] + boff, &A[(size_t)(brow + row) * K + k0 + lc4 * 4],
                       (brow + row < M) ? 16 : 0);
            CP_ASYNC16(baseB[i] + boff, &Wt[(size_t)(bcol + row) * K + k0 + lc4 * 4], 16);
        }
        CP_COMMIT();
    };

    issue(0);
    if (NC > 1) issue(1);
    for (int c = 0; c < NC; ++c) {
        if (c + 1 < NC) CP_WAIT1(); else CP_WAIT0();
        __syncthreads();
        if (c + 2 < NC) issue(c + 2);

        const uint32_t* bufA = reinterpret_cast<const uint32_t*>(sAbase + (c % 3) * TILE_F);
        const uint32_t* bufB = reinterpret_cast<const uint32_t*>(sBbase + (c % 3) * TILE_F);
#pragma unroll
        for (int s = 0; s < 4; s++) {
            const int k = s * 8;
            uint32_t afr[2][4];
#pragma unroll
            for (int i = 0; i < 2; i++) {
                int r = wm * 32 + i * 16 + g;
                afr[i][0] = f2tf32(__uint_as_float(bufA[(r + 0) * LDSS + k + tig]));
                afr[i][1] = f2tf32(__uint_as_float(bufA[(r + 8) * LDSS + k + tig]));
                afr[i][2] = f2tf32(__uint_as_float(bufA[(r + 0) * LDSS + k + tig + 4]));
                afr[i][3] = f2tf32(__uint_as_float(bufA[(r + 8) * LDSS + k + tig + 4]));
            }
#pragma unroll
            for (int j = 0; j < 8; j++) {
                int n = wn * 64 + j * 8 + g;
                uint32_t bfr[2];
                bfr[0] = bufB[n * LDSS + k + tig];
                bfr[1] = bufB[n * LDSS + k + tig + 4];
                mma_16n8k8(acc[0][j], afr[0], bfr);
                mma_16n8k8(acc[1][j], afr[1], bfr);
            }
        }
    }

    // epilogue: float2 stores, fused bias (+relu | +residual)
#pragma unroll
    for (int i = 0; i < 2; i++) {
        int r0 = brow + wm * 32 + i * 16 + g;
#pragma unroll
        for (int j = 0; j < 8; j++) {
            int col = bcol + wn * 64 + j * 8 + 2 * tig;
            float b0 = __ldg(&bias[col]);
            float b1 = __ldg(&bias[col + 1]);
            if (r0 < M) {
                float v0 = acc[i][j][0] + b0;
                float v1 = acc[i][j][1] + b1;
                if (MODE == 1) { v0 = fmaxf(v0, 0.f); v1 = fmaxf(v1, 0.f); }
                if (MODE == 2) {
                    const float2 rr = *reinterpret_cast<const float2*>(&res[(size_t)r0 * N + col]);
                    v0 += rr.x; v1 += rr.y;
                }
                *reinterpret_cast<float2*>(&C[(size_t)r0 * N + col]) = make_float2(v0, v1);
            }
            int r1 = r0 + 8;
            if (r1 < M) {
                float v0 = acc[i][j][2] + b0;
                float v1 = acc[i][j][3] + b1;
                if (MODE == 1) { v0 = fmaxf(v0, 0.f); v1 = fmaxf(v1, 0.f); }
                if (MODE == 2) {
                    const float2 rr = *reinterpret_cast<const float2*>(&res[(size_t)r1 * N + col]);
                    v0 += rr.x; v1 += rr.y;
                }
                *reinterpret_cast<float2*>(&C[(size_t)r1 * N + col]) = make_float2(v0, v1);
            }
        }
    }
}

// ---------------------------------------------------------------------------
// Merged transposes (+ tf32 rounding). 32x8 threads.
// transpose_small: Wval(64) | Woff(64) | Wattn(32) | Wout(64) | bias concat(1)
// transpose_big:   W1(256) | W2(256)
// ---------------------------------------------------------------------------
__global__ void transpose_small_k(const float* __restrict__ Wval, const float* __restrict__ Woff,
                                  const float* __restrict__ Wattn, const float* __restrict__ Wout,
                                  const float* __restrict__ boff, const float* __restrict__ battn,
                                  float* __restrict__ wtv, float* __restrict__ wtoa,
                                  float* __restrict__ wtO, float* __restrict__ bias_oa) {
    __shared__ float t[32][33];
    int blk = blockIdx.x;
    int x = threadIdx.x, y = threadIdx.y;
    if (blk == 224) {
        int tt = y * 32 + x;
        for (int i = tt; i < 384; i += 256)
            bias_oa[i] = (i < 256) ? boff[i] : battn[i - 256];
        return;
    }
    const float* W; float* Wt; int K, N, lb;
    if (blk < 64)       { W = Wval;  Wt = wtv;              K = 256; N = 256; lb = blk; }
    else if (blk < 128) { W = Woff;  Wt = wtoa;             K = 256; N = 256; lb = blk - 64; }
    else if (blk < 160) { W = Wattn; Wt = wtoa + 256 * 256; K = 256; N = 128; lb = blk - 128; }
    else                { W = Wout;  Wt = wtO;              K = 256; N = 256; lb = blk - 160; }
    int ntx = N >> 5;
    int n0 = (lb % ntx) * 32, k0 = (lb / ntx) * 32;
#pragma unroll
    for (int i = 0; i < 32; i += 8)
        t[y + i][x] = W[(size_t)(k0 + y + i) * N + n0 + x];
    __syncthreads();
#pragma unroll
    for (int i = 0; i < 32; i += 8)
        Wt[(size_t)(n0 + y + i) * K + k0 + x] = __uint_as_float(f2tf32(t[x][y + i]));
}

__global__ void transpose_big_k(const float* __restrict__ W1, const float* __restrict__ W2,
                                float* __restrict__ wt1, float* __restrict__ wt2) {
    __shared__ float t[32][33];
    int blk = blockIdx.x;
    int x = threadIdx.x, y = threadIdx.y;
    const float* W; float* Wt; int K, N, lb;
    if (blk < 256) { W = W1; Wt = wt1; K = 256;  N = 1024; lb = blk; }
    else           { W = W2; Wt = wt2; K = 1024; N = 256;  lb = blk - 256; }
    int ntx = N >> 5;
    int n0 = (lb % ntx) * 32, k0 = (lb / ntx) * 32;
#pragma unroll
    for (int i = 0; i < 32; i += 8)
        t[y + i][x] = W[(size_t)(k0 + y + i) * N + n0 + x];
    __syncthreads();
#pragma unroll
    for (int i = 0; i < 32; i += 8)
        Wt[(size_t)(n0 + y + i) * K + k0 + x] = __uint_as_float(f2tf32(t[x][y + i]));
}

// ---------------------------------------------------------------------------
// Elementwise add
// ---------------------------------------------------------------------------
__global__ void add_k(const float4* __restrict__ a, const float4* __restrict__ b,
                      float4* __restrict__ c, int n4) {
    int i = blockIdx.x * blockDim.x + threadIdx.x;
    if (i >= n4) return;
    float4 x = a[i], y = b[i];
    c[i] = make_float4(x.x + y.x, x.y + y.y, x.z + y.z, x.w + y.w);
}

// ---------------------------------------------------------------------------
// Deformable sampling: one warp per (b,q,h); lane = (point p, channel-quad c4).
// Softmax over the 16 (level,point) logits fused via shuffles.
// Reads fused oa buffer: [row][0:256] offsets, [row][256:384] logits.
// ---------------------------------------------------------------------------
__global__ __launch_bounds__(256)
void sample_k(const float* __restrict__ v, const float* __restrict__ oa,
              const float* __restrict__ ref, float* __restrict__ out) {
    int warp = (blockIdx.x * blockDim.x + threadIdx.x) >> 5;
    int lane = threadIdx.x & 31;
    if (warp >= MROWS * NHEAD) return;
    int h   = warp & 7;
    int row = warp >> 3;
    int b   = row / LTOT;
    int p   = lane >> 3;      // point 0..3
    int c4  = lane & 7;       // channel quad 0..7

    const int HS[4] = {100, 50, 25, 13};
    const int ST[4] = {0, 10000, 12500, 13125};

    const float* offp = oa + (size_t)row * 384 + h * 32;
    const float* lgp  = oa + (size_t)row * 384 + 256 + h * 16;
    const float* refp = ref + (size_t)row * 8;

    float lg[4];
#pragma unroll
    for (int l = 0; l < 4; l++) lg[l] = __ldg(lgp + l * 4 + p);
    float mx = fmaxf(fmaxf(lg[0], lg[1]), fmaxf(lg[2], lg[3]));
    mx = fmaxf(mx, __shfl_xor_sync(0xffffffffu, mx, 8));
    mx = fmaxf(mx, __shfl_xor_sync(0xffffffffu, mx, 16));
    float e[4], s = 0.f;
#pragma unroll
    for (int l = 0; l < 4; l++) { e[l] = __expf(lg[l] - mx); s += e[l]; }
    s += __shfl_xor_sync(0xffffffffu, s, 8);
    s += __shfl_xor_sync(0xffffffffu, s, 16);
    const float inv = 1.f / s;

    float ax = 0.f, ay = 0.f, az = 0.f, aq = 0.f;
#pragma unroll
    for (int l = 0; l < 4; l++) {
        const int H = HS[l], W = HS[l], S = ST[l];
        float rx = __ldg(refp + l * 2 + 0);
        float ry = __ldg(refp + l * 2 + 1);
        float ox = __ldg(offp + l * 8 + p * 2 + 0);
        float oy = __ldg(offp + l * 8 + p * 2 + 1);
        float aww = e[l] * inv;
        float x = rx * (float)W + ox - 0.5f;
        float y = ry * (float)H + oy - 0.5f;
        float x0f = floorf(x), y0f = floorf(y);
        float lx = x - x0f, ly = y - y0f;
        int x0 = (int)x0f, y0 = (int)y0f;
        float w00 = (1.f - lx) * (1.f - ly) * aww;
        float w10 = lx * (1.f - ly) * aww;
        float w01 = (1.f - lx) * ly * aww;
        float w11 = lx * ly * aww;
        bool vx0 = (x0 >= 0) && (x0 < W);
        bool vx1 = (x0 + 1 >= 0) && (x0 + 1 < W);
        bool vy0 = (y0 >= 0) && (y0 < H);
        bool vy1 = (y0 + 1 >= 0) && (y0 + 1 < H);
        const float4* vb = reinterpret_cast<const float4*>(
            v + ((size_t)(b * LTOT + S) * NHEAD + h) * DHEAD) + c4;
        const int str4 = NHEAD * DHEAD / 4;  // 64 float4 per spatial index
        if (vy0 && vx0) {
            float4 t = __ldg(vb + (size_t)(y0 * W + x0) * str4);
            ax += w00 * t.x; ay += w00 * t.y; az += w00 * t.z; aq += w00 * t.w;
        }
        if (vy0 && vx1) {
            float4 t = __ldg(vb + (size_t)(y0 * W + x0 + 1) * str4);
            ax += w10 * t.x; ay += w10 * t.y; az += w10 * t.z; aq += w10 * t.w;
        }
        if (vy1 && vx0) {
            float4 t = __ldg(vb + (size_t)((y0 + 1) * W + x0) * str4);
            ax += w01 * t.x; ay += w01 * t.y; az += w01 * t.z; aq += w01 * t.w;
        }
        if (vy1 && vx1) {
            float4 t = __ldg(vb + (size_t)((y0 + 1) * W + x0 + 1) * str4);
            ax += w11 * t.x; ay += w11 * t.y; az += w11 * t.z; aq += w11 * t.w;
        }
    }
#pragma unroll
    for (int o = 8; o <= 16; o <<= 1) {
        ax += __shfl_xor_sync(0xffffffffu, ax, o);
        ay += __shfl_xor_sync(0xffffffffu, ay, o);
        az += __shfl_xor_sync(0xffffffffu, az, o);
        aq += __shfl_xor_sync(0xffffffffu, aq, o);
    }
    if (p == 0)
        *reinterpret_cast<float4*>(&out[(size_t)row * DMODEL + h * DHEAD + c4 * 4]) =
            make_float4(ax, ay, az, aq);
}

// ---------------------------------------------------------------------------
// LayerNorm over 256
// ---------------------------------------------------------------------------
__global__ __launch_bounds__(256)
void ln_k(const float* __restrict__ in, const float* __restrict__ g,
          const float* __restrict__ b, float* __restrict__ out) {
    int row = blockIdx.x;
    int t = threadIdx.x;
    float v = in[(size_t)row * DMODEL + t];
    float s = v, s2 = v * v;
#pragma unroll
    for (int o = 16; o > 0; o >>= 1) {
        s  += __shfl_xor_sync(0xffffffff, s,  o);
        s2 += __shfl_xor_sync(0xffffffff, s2, o);
    }
    __shared__ float sh[8], sh2[8];
    int wid = t >> 5, lane = t & 31;
    if (lane == 0) { sh[wid] = s; sh2[wid] = s2; }
    __syncthreads();
    float ts = 0.f, ts2 = 0.f;
#pragma unroll
    for (int i = 0; i < 8; i++) { ts += sh[i]; ts2 += sh2[i]; }
    float mu = ts * (1.f / DMODEL);
    float var = ts2 * (1.f / DMODEL) - mu * mu;
    float inv = rsqrtf(var + 1e-5f);
    out[(size_t)row * DMODEL + t] = (v - mu) * inv * g[t] + b[t];
}

// ---------------------------------------------------------------------------
// Launch
// ---------------------------------------------------------------------------
extern "C" void kernel_launch(void* const* d_in, const int* in_sizes, int n_in,
                              void* d_out, int out_size) {
    const float* src   = (const float*)d_in[0];
    const float* pos   = (const float*)d_in[1];
    const float* ref   = (const float*)d_in[2];
    const float* Woff  = (const float*)d_in[5];
    const float* boff  = (const float*)d_in[6];
    const float* Wattn = (const float*)d_in[7];
    const float* battn = (const float*)d_in[8];
    const float* Wval  = (const float*)d_in[9];
    const float* bval  = (const float*)d_in[10];
    const float* Wout  = (const float*)d_in[11];
    const float* bout  = (const float*)d_in[12];
    const float* lsg   = (const float*)d_in[13];
    const float* lsb   = (const float*)d_in[14];
    const float* W1    = (const float*)d_in[15];
    const float* b1    = (const float*)d_in[16];
    const float* W2    = (const float*)d_in[17];
    const float* b2    = (const float*)d_in[18];
    const float* lfg   = (const float*)d_in[19];
    const float* lfb   = (const float*)d_in[20];
    float* out = (float*)d_out;

    float *q, *v, *oa, *samp, *tmp, *x, *h1;
    float *wtv, *wtoa, *wtO, *wt1, *wt2, *boa;
    cudaGetSymbolAddress((void**)&q,    g_q);
    cudaGetSymbolAddress((void**)&v,    g_v);
    cudaGetSymbolAddress((void**)&oa,   g_oa);
    cudaGetSymbolAddress((void**)&samp, g_samp);
    cudaGetSymbolAddress((void**)&tmp,  g_tmp);
    cudaGetSymbolAddress((void**)&x,    g_x);
    cudaGetSymbolAddress((void**)&h1,   g_h1);
    cudaGetSymbolAddress((void**)&wtv,  g_wt_val);
    cudaGetSymbolAddress((void**)&wtoa, g_wt_oa);
    cudaGetSymbolAddress((void**)&wtO,  g_wt_out);
    cudaGetSymbolAddress((void**)&wt1,  g_wt_1);
    cudaGetSymbolAddress((void**)&wt2,  g_wt_2);
    cudaGetSymbolAddress((void**)&boa,  g_bias_oa);

    cudaFuncSetAttribute(gemm_mma<0>, cudaFuncAttributeMaxDynamicSharedMemorySize, GEMM_SMEM);
    cudaFuncSetAttribute(gemm_mma<1>, cudaFuncAttributeMaxDynamicSharedMemorySize, GEMM_SMEM);
    cudaFuncSetAttribute(gemm_mma<2>, cudaFuncAttributeMaxDynamicSharedMemorySize, GEMM_SMEM);

    const int M = MROWS;
    const int mblk = (M + 127) / 128;   // 416
    dim3 tb(32, 8);

    // 1. small transposes + bias concat
    transpose_small_k<<<225, tb>>>(Wval, Woff, Wattn, Wout, boff, battn,
                                   wtv, wtoa, wtO, boa);
    // 2. big transposes (W1, W2)
    transpose_big_k<<<512, tb>>>(W1, W2, wt1, wt2);
    // 3. q = src + pos
    {
        int n4 = M * DMODEL / 4;
        add_k<<<(n4 + 255) / 256, 256>>>((const float4*)src, (const float4*)pos,
                                         (float4*)q, n4);
    }
    // 4. v = src @ Wval + bval
    gemm_mma<0><<<dim3(2, mblk), 256, GEMM_SMEM>>>(src, wtv, bval, nullptr, v, M, 256, 256);
    // 5. oa = q @ [Woff|Wattn] + [boff|battn]   (fused, N=384)
    gemm_mma<0><<<dim3(3, mblk), 256, GEMM_SMEM>>>(q, wtoa, boa, nullptr, oa, M, 384, 256);
    // 6. deformable sampling + fused softmax   <-- ncu capture slot
    sample_k<<<(M * NHEAD) / 8, 256>>>(v, oa, ref, samp);
    // 7. tmp = samp @ Wout + bout + src
    gemm_mma<2><<<dim3(2, mblk), 256, GEMM_SMEM>>>(samp, wtO, bout, src, tmp, M, 256, 256);
    // 8. x = LN(tmp)
    ln_k<<<M, 256>>>(tmp, lsg, lsb, x);
    // 9. h1 = relu(x @ W1 + b1)
    gemm_mma<1><<<dim3(8, mblk), 256, GEMM_SMEM>>>(x, wt1, b1, nullptr, h1, M, 1024, 256);
    // 10. tmp = h1 @ W2 + b2 + x
    gemm_mma<2><<<dim3(2, mblk), 256, GEMM_SMEM>>>(h1, wt2, b2, x, tmp, M, 256, 1024);
    // 11. out = LN(tmp)
    ln_k<<<M, 256>>>(tmp, lfg, lfb, out);
}

// round 7
// speedup vs baseline: 2.9714x; 1.0262x over previous
#include <cuda_runtime.h>
#include <cstdint>

// ---------------------------------------------------------------------------
// Problem constants
// ---------------------------------------------------------------------------
#define BATCH 4
#define LTOT  13294
#define MROWS (BATCH * LTOT)   // 53176
#define DMODEL 256
#define DFFN   1024
#define NHEAD  8
#define NLVL   4
#define NPTS   4
#define DHEAD  32

// ---------------------------------------------------------------------------
// Scratch (device globals; no runtime allocation allowed)
// ---------------------------------------------------------------------------
__device__ float g_q   [MROWS * DMODEL];
__device__ float g_v   [MROWS * DMODEL];
__device__ float g_oa  [MROWS * 384];     // fused offsets(256) + attn logits(128)
__device__ float g_samp[MROWS * DMODEL];
__device__ float g_tmp [MROWS * DMODEL];
__device__ float g_x   [MROWS * DMODEL];
__device__ float g_h1  [MROWS * DFFN];
// transposed weights [N, K] (tf32-rounded)
__device__ float g_wt_val [DMODEL * DMODEL];
__device__ float g_wt_oa  [384 * DMODEL];
__device__ float g_wt_out [DMODEL * DMODEL];
__device__ float g_wt_1   [DFFN * DMODEL];
__device__ float g_wt_2   [DMODEL * DFFN];
__device__ float g_bias_oa[384];

// ---------------------------------------------------------------------------
// Helpers
// ---------------------------------------------------------------------------
__device__ __forceinline__ uint32_t f2tf32(float f) {
    uint32_t r;
    asm("cvt.rna.tf32.f32 %0, %1;" : "=r"(r) : "f"(f));
    return r;
}

__device__ __forceinline__ void mma_16n8k8(float* d, const uint32_t* a, const uint32_t* b) {
    asm volatile(
        "mma.sync.aligned.m16n8k8.row.col.f32.tf32.tf32.f32 "
        "{%0,%1,%2,%3}, {%4,%5,%6,%7}, {%8,%9}, {%0,%1,%2,%3};"
        : "+f"(d[0]), "+f"(d[1]), "+f"(d[2]), "+f"(d[3])
        : "r"(a[0]), "r"(a[1]), "r"(a[2]), "r"(a[3]), "r"(b[0]), "r"(b[1]));
}

#define LDSM_X4(r0, r1, r2, r3, addr) \
    asm volatile("ldmatrix.sync.aligned.m8n8.x4.shared.b16 {%0,%1,%2,%3}, [%4];" \
        : "=r"(r0), "=r"(r1), "=r"(r2), "=r"(r3) : "r"(addr))

#define CP_ASYNC16(dst, src, nbytes) \
    asm volatile("cp.async.cg.shared.global [%0], [%1], 16, %2;" \
        :: "r"(dst), "l"(src), "r"(nbytes))
#define CP_COMMIT() asm volatile("cp.async.commit_group;")
#define CP_WAIT1()  asm volatile("cp.async.wait_group 1;")
#define CP_WAIT0()  asm volatile("cp.async.wait_group 0;")

// ---------------------------------------------------------------------------
// tf32 mma.sync GEMM, 3-stage cp.async pipeline, ldmatrix fragment loads.
// C[M,N] = A[M,K] @ Wt[N,K]^T + bias (+relu | +res)
// 128x128 CTA tile, BK=32, 8 warps of 32x64, m16n8k8.
// Wt pre-rounded to tf32; A rounded (RNA) after ldmatrix.
// MODE: 0 = bias, 1 = bias+relu, 2 = bias+residual
// ---------------------------------------------------------------------------
#define LDSS 36                      // padded smem row stride (floats)
#define TILE_F (128 * LDSS)          // floats per tile buffer
#define TILE_BYTES (TILE_F * 4)      // 18432
#define GEMM_SMEM (6 * TILE_BYTES)   // A0..2, B0..2 -> 110592 bytes

template <int MODE>
__global__ __launch_bounds__(256)
void gemm_mma(const float* __restrict__ A, const float* __restrict__ Wt,
              const float* __restrict__ bias, const float* __restrict__ res,
              float* __restrict__ C, int M, int N, int K) {
    extern __shared__ float smem[];
    float* sAbase = smem;                 // 3 tiles
    float* sBbase = smem + 3 * TILE_F;    // 3 tiles

    const int tid  = threadIdx.x;
    const int wid  = tid >> 5;
    const int lane = tid & 31;
    const int g    = lane >> 2;      // groupID 0..7
    const int tig  = lane & 3;       // thread-in-group 0..3
    const int wm   = wid >> 1;       // 0..3 (32-row slab)
    const int wn   = wid & 1;        // 0..1 (64-col slab)
    const int brow = blockIdx.y * 128;
    const int bcol = blockIdx.x * 128;
    const int NC   = K >> 5;

    const int lrow[4] = {(tid + 0) >> 3, (tid + 256) >> 3, (tid + 512) >> 3, (tid + 768) >> 3};
    const int lc4 = tid & 7;

    // cp.async dst addresses (tile 0 base; add (c%3)*TILE_BYTES per chunk)
    uint32_t cpA[4], cpB[4];
#pragma unroll
    for (int i = 0; i < 4; i++) {
        cpA[i] = (uint32_t)__cvta_generic_to_shared(&sAbase[lrow[i] * LDSS + lc4 * 4]);
        cpB[i] = (uint32_t)__cvta_generic_to_shared(&sBbase[lrow[i] * LDSS + lc4 * 4]);
    }

    // ldmatrix lane-address offsets (bytes, relative to tile base; add s*32 per k-step)
    // A (per i slab of 16 rows): lanes 0-15 -> rows m+0..15 @ k+0, lanes 16-31 -> same rows @ k+4
    uint32_t aAddr0 = (uint32_t)__cvta_generic_to_shared(sAbase);
    uint32_t bAddr0 = (uint32_t)__cvta_generic_to_shared(sBbase);
    uint32_t aoff[2];
#pragma unroll
    for (int i = 0; i < 2; i++)
        aoff[i] = (uint32_t)(((wm * 32 + i * 16 + (lane & 15)) * LDSS + ((lane >> 4) << 2)) * 4);
    // B (per j2 pair of 8-col groups): lanes 0-7 n+0..7 @k, 8-15 n+0..7 @k+4,
    //                                  16-23 n+8..15 @k, 24-31 n+8..15 @k+4
    uint32_t boff[4];
#pragma unroll
    for (int j2 = 0; j2 < 4; j2++)
        boff[j2] = (uint32_t)(((wn * 64 + j2 * 16 + (lane & 7) + ((lane >> 4) << 3)) * LDSS
                               + (((lane >> 3) & 1) << 2)) * 4);

    float acc[2][8][4];
#pragma unroll
    for (int i = 0; i < 2; i++)
#pragma unroll
        for (int j = 0; j < 8; j++)
#pragma unroll
            for (int t = 0; t < 4; t++) acc[i][j][t] = 0.f;

    auto issue = [&](int ck) {
        const uint32_t bo = (uint32_t)(ck % 3) * TILE_BYTES;
        const int k0 = ck << 5;
#pragma unroll
        for (int i = 0; i < 4; i++) {
            int row = lrow[i];
            CP_ASYNC16(cpA[i] + bo, &A[(size_t)(brow + row) * K + k0 + lc4 * 4],
                       (brow + row < M) ? 16 : 0);
            CP_ASYNC16(cpB[i] + bo, &Wt[(size_t)(bcol + row) * K + k0 + lc4 * 4], 16);
        }
        CP_COMMIT();
    };

    issue(0);
    if (NC > 1) issue(1);
    for (int c = 0; c < NC; ++c) {
        if (c + 1 < NC) CP_WAIT1(); else CP_WAIT0();
        __syncthreads();
        if (c + 2 < NC) issue(c + 2);

        const uint32_t tb = (uint32_t)(c % 3) * TILE_BYTES;
        const uint32_t aB = aAddr0 + tb;
        const uint32_t bB = bAddr0 + tb;
#pragma unroll
        for (int s = 0; s < 4; s++) {
            const uint32_t ks = (uint32_t)(s * 32);
            uint32_t afr[2][4];
#pragma unroll
            for (int i = 0; i < 2; i++) {
                uint32_t t0, t1, t2, t3;
                LDSM_X4(t0, t1, t2, t3, aB + aoff[i] + ks);
                afr[i][0] = f2tf32(__uint_as_float(t0));
                afr[i][1] = f2tf32(__uint_as_float(t1));
                afr[i][2] = f2tf32(__uint_as_float(t2));
                afr[i][3] = f2tf32(__uint_as_float(t3));
            }
#pragma unroll
            for (int j2 = 0; j2 < 4; j2++) {
                uint32_t b0[2], b1[2];
                LDSM_X4(b0[0], b0[1], b1[0], b1[1], bB + boff[j2] + ks);
                mma_16n8k8(acc[0][2 * j2 + 0], afr[0], b0);
                mma_16n8k8(acc[1][2 * j2 + 0], afr[1], b0);
                mma_16n8k8(acc[0][2 * j2 + 1], afr[0], b1);
                mma_16n8k8(acc[1][2 * j2 + 1], afr[1], b1);
            }
        }
    }

    // epilogue: float2 stores, fused bias (+relu | +residual)
#pragma unroll
    for (int i = 0; i < 2; i++) {
        int r0 = brow + wm * 32 + i * 16 + g;
#pragma unroll
        for (int j = 0; j < 8; j++) {
            int col = bcol + wn * 64 + j * 8 + 2 * tig;
            float b0 = __ldg(&bias[col]);
            float b1 = __ldg(&bias[col + 1]);
            if (r0 < M) {
                float v0 = acc[i][j][0] + b0;
                float v1 = acc[i][j][1] + b1;
                if (MODE == 1) { v0 = fmaxf(v0, 0.f); v1 = fmaxf(v1, 0.f); }
                if (MODE == 2) {
                    const float2 rr = *reinterpret_cast<const float2*>(&res[(size_t)r0 * N + col]);
                    v0 += rr.x; v1 += rr.y;
                }
                *reinterpret_cast<float2*>(&C[(size_t)r0 * N + col]) = make_float2(v0, v1);
            }
            int r1 = r0 + 8;
            if (r1 < M) {
                float v0 = acc[i][j][2] + b0;
                float v1 = acc[i][j][3] + b1;
                if (MODE == 1) { v0 = fmaxf(v0, 0.f); v1 = fmaxf(v1, 0.f); }
                if (MODE == 2) {
                    const float2 rr = *reinterpret_cast<const float2*>(&res[(size_t)r1 * N + col]);
                    v0 += rr.x; v1 += rr.y;
                }
                *reinterpret_cast<float2*>(&C[(size_t)r1 * N + col]) = make_float2(v0, v1);
            }
        }
    }
}

// ---------------------------------------------------------------------------
// Merged transposes (+ tf32 rounding). 32x8 threads.
// ---------------------------------------------------------------------------
__global__ void transpose_small_k(const float* __restrict__ Wval, const float* __restrict__ Woff,
                                  const float* __restrict__ Wattn, const float* __restrict__ Wout,
                                  const float* __restrict__ boff, const float* __restrict__ battn,
                                  float* __restrict__ wtv, float* __restrict__ wtoa,
                                  float* __restrict__ wtO, float* __restrict__ bias_oa) {
    __shared__ float t[32][33];
    int blk = blockIdx.x;
    int x = threadIdx.x, y = threadIdx.y;
    if (blk == 224) {
        int tt = y * 32 + x;
        for (int i = tt; i < 384; i += 256)
            bias_oa[i] = (i < 256) ? boff[i] : battn[i - 256];
        return;
    }
    const float* W; float* Wt; int K, N, lb;
    if (blk < 64)       { W = Wval;  Wt = wtv;              K = 256; N = 256; lb = blk; }
    else if (blk < 128) { W = Woff;  Wt = wtoa;             K = 256; N = 256; lb = blk - 64; }
    else if (blk < 160) { W = Wattn; Wt = wtoa + 256 * 256; K = 256; N = 128; lb = blk - 128; }
    else                { W = Wout;  Wt = wtO;              K = 256; N = 256; lb = blk - 160; }
    int ntx = N >> 5;
    int n0 = (lb % ntx) * 32, k0 = (lb / ntx) * 32;
#pragma unroll
    for (int i = 0; i < 32; i += 8)
        t[y + i][x] = W[(size_t)(k0 + y + i) * N + n0 + x];
    __syncthreads();
#pragma unroll
    for (int i = 0; i < 32; i += 8)
        Wt[(size_t)(n0 + y + i) * K + k0 + x] = __uint_as_float(f2tf32(t[x][y + i]));
}

__global__ void transpose_big_k(const float* __restrict__ W1, const float* __restrict__ W2,
                                float* __restrict__ wt1, float* __restrict__ wt2) {
    __shared__ float t[32][33];
    int blk = blockIdx.x;
    int x = threadIdx.x, y = threadIdx.y;
    const float* W; float* Wt; int K, N, lb;
    if (blk < 256) { W = W1; Wt = wt1; K = 256;  N = 1024; lb = blk; }
    else           { W = W2; Wt = wt2; K = 1024; N = 256;  lb = blk - 256; }
    int ntx = N >> 5;
    int n0 = (lb % ntx) * 32, k0 = (lb / ntx) * 32;
#pragma unroll
    for (int i = 0; i < 32; i += 8)
        t[y + i][x] = W[(size_t)(k0 + y + i) * N + n0 + x];
    __syncthreads();
#pragma unroll
    for (int i = 0; i < 32; i += 8)
        Wt[(size_t)(n0 + y + i) * K + k0 + x] = __uint_as_float(f2tf32(t[x][y + i]));
}

// ---------------------------------------------------------------------------
// Elementwise add
// ---------------------------------------------------------------------------
__global__ void add_k(const float4* __restrict__ a, const float4* __restrict__ b,
                      float4* __restrict__ c, int n4) {
    int i = blockIdx.x * blockDim.x + threadIdx.x;
    if (i >= n4) return;
    float4 x = a[i], y = b[i];
    c[i] = make_float4(x.x + y.x, x.y + y.y, x.z + y.z, x.w + y.w);
}

// ---------------------------------------------------------------------------
// Deformable sampling: one warp per (b,q,h); lane = (point p, channel-quad c4).
// Softmax over the 16 (level,point) logits fused via shuffles.
// ---------------------------------------------------------------------------
__global__ __launch_bounds__(256)
void sample_k(const float* __restrict__ v, const float* __restrict__ oa,
              const float* __restrict__ ref, float* __restrict__ out) {
    int warp = (blockIdx.x * blockDim.x + threadIdx.x) >> 5;
    int lane = threadIdx.x & 31;
    if (warp >= MROWS * NHEAD) return;
    int h   = warp & 7;
    int row = warp >> 3;
    int b   = row / LTOT;
    int p   = lane >> 3;      // point 0..3
    int c4  = lane & 7;       // channel quad 0..7

    const int HS[4] = {100, 50, 25, 13};
    const int ST[4] = {0, 10000, 12500, 13125};

    const float* offp = oa + (size_t)row * 384 + h * 32;
    const float* lgp  = oa + (size_t)row * 384 + 256 + h * 16;
    const float* refp = ref + (size_t)row * 8;

    float lg[4];
#pragma unroll
    for (int l = 0; l < 4; l++) lg[l] = __ldg(lgp + l * 4 + p);
    float mx = fmaxf(fmaxf(lg[0], lg[1]), fmaxf(lg[2], lg[3]));
    mx = fmaxf(mx, __shfl_xor_sync(0xffffffffu, mx, 8));
    mx = fmaxf(mx, __shfl_xor_sync(0xffffffffu, mx, 16));
    float e[4], s = 0.f;
#pragma unroll
    for (int l = 0; l < 4; l++) { e[l] = __expf(lg[l] - mx); s += e[l]; }
    s += __shfl_xor_sync(0xffffffffu, s, 8);
    s += __shfl_xor_sync(0xffffffffu, s, 16);
    const float inv = 1.f / s;

    float ax = 0.f, ay = 0.f, az = 0.f, aq = 0.f;
#pragma unroll
    for (int l = 0; l < 4; l++) {
        const int H = HS[l], W = HS[l], S = ST[l];
        float rx = __ldg(refp + l * 2 + 0);
        float ry = __ldg(refp + l * 2 + 1);
        float ox = __ldg(offp + l * 8 + p * 2 + 0);
        float oy = __ldg(offp + l * 8 + p * 2 + 1);
        float aww = e[l] * inv;
        float x = rx * (float)W + ox - 0.5f;
        float y = ry * (float)H + oy - 0.5f;
        float x0f = floorf(x), y0f = floorf(y);
        float lx = x - x0f, ly = y - y0f;
        int x0 = (int)x0f, y0 = (int)y0f;
        float w00 = (1.f - lx) * (1.f - ly) * aww;
        float w10 = lx * (1.f - ly) * aww;
        float w01 = (1.f - lx) * ly * aww;
        float w11 = lx * ly * aww;
        bool vx0 = (x0 >= 0) && (x0 < W);
        bool vx1 = (x0 + 1 >= 0) && (x0 + 1 < W);
        bool vy0 = (y0 >= 0) && (y0 < H);
        bool vy1 = (y0 + 1 >= 0) && (y0 + 1 < H);
        const float4* vb = reinterpret_cast<const float4*>(
            v + ((size_t)(b * LTOT + S) * NHEAD + h) * DHEAD) + c4;
        const int str4 = NHEAD * DHEAD / 4;  // 64 float4 per spatial index
        if (vy0 && vx0) {
            float4 t = __ldg(vb + (size_t)(y0 * W + x0) * str4);
            ax += w00 * t.x; ay += w00 * t.y; az += w00 * t.z; aq += w00 * t.w;
        }
        if (vy0 && vx1) {
            float4 t = __ldg(vb + (size_t)(y0 * W + x0 + 1) * str4);
            ax += w10 * t.x; ay += w10 * t.y; az += w10 * t.z; aq += w10 * t.w;
        }
        if (vy1 && vx0) {
            float4 t = __ldg(vb + (size_t)((y0 + 1) * W + x0) * str4);
            ax += w01 * t.x; ay += w01 * t.y; az += w01 * t.z; aq += w01 * t.w;
        }
        if (vy1 && vx1) {
            float4 t = __ldg(vb + (size_t)((y0 + 1) * W + x0 + 1) * str4);
            ax += w11 * t.x; ay += w11 * t.y; az += w11 * t.z; aq += w11 * t.w;
        }
    }
#pragma unroll
    for (int o = 8; o <= 16; o <<= 1) {
        ax += __shfl_xor_sync(0xffffffffu, ax, o);
        ay += __shfl_xor_sync(0xffffffffu, ay, o);
        az += __shfl_xor_sync(0xffffffffu, az, o);
        aq += __shfl_xor_sync(0xffffffffu, aq, o);
    }
    if (p == 0)
        *reinterpret_cast<float4*>(&out[(size_t)row * DMODEL + h * DHEAD + c4 * 4]) =
            make_float4(ax, ay, az, aq);
}

// ---------------------------------------------------------------------------
// LayerNorm over 256
// ---------------------------------------------------------------------------
__global__ __launch_bounds__(256)
void ln_k(const float* __restrict__ in, const float* __restrict__ g,
          const float* __restrict__ b, float* __restrict__ out) {
    int row = blockIdx.x;
    int t = threadIdx.x;
    float v = in[(size_t)row * DMODEL + t];
    float s = v, s2 = v * v;
#pragma unroll
    for (int o = 16; o > 0; o >>= 1) {
        s  += __shfl_xor_sync(0xffffffff, s,  o);
        s2 += __shfl_xor_sync(0xffffffff, s2, o);
    }
    __shared__ float sh[8], sh2[8];
    int wid = t >> 5, lane = t & 31;
    if (lane == 0) { sh[wid] = s; sh2[wid] = s2; }
    __syncthreads();
    float ts = 0.f, ts2 = 0.f;
#pragma unroll
    for (int i = 0; i < 8; i++) { ts += sh[i]; ts2 += sh2[i]; }
    float mu = ts * (1.f / DMODEL);
    float var = ts2 * (1.f / DMODEL) - mu * mu;
    float inv = rsqrtf(var + 1e-5f);
    out[(size_t)row * DMODEL + t] = (v - mu) * inv * g[t] + b[t];
}

// ---------------------------------------------------------------------------
// Launch
// ---------------------------------------------------------------------------
extern "C" void kernel_launch(void* const* d_in, const int* in_sizes, int n_in,
                              void* d_out, int out_size) {
    const float* src   = (const float*)d_in[0];
    const float* pos   = (const float*)d_in[1];
    const float* ref   = (const float*)d_in[2];
    const float* Woff  = (const float*)d_in[5];
    const float* boff  = (const float*)d_in[6];
    const float* Wattn = (const float*)d_in[7];
    const float* battn = (const float*)d_in[8];
    const float* Wval  = (const float*)d_in[9];
    const float* bval  = (const float*)d_in[10];
    const float* Wout  = (const float*)d_in[11];
    const float* bout  = (const float*)d_in[12];
    const float* lsg   = (const float*)d_in[13];
    const float* lsb   = (const float*)d_in[14];
    const float* W1    = (const float*)d_in[15];
    const float* b1    = (const float*)d_in[16];
    const float* W2    = (const float*)d_in[17];
    const float* b2    = (const float*)d_in[18];
    const float* lfg   = (const float*)d_in[19];
    const float* lfb   = (const float*)d_in[20];
    float* out = (float*)d_out;

    float *q, *v, *oa, *samp, *tmp, *x, *h1;
    float *wtv, *wtoa, *wtO, *wt1, *wt2, *boa;
    cudaGetSymbolAddress((void**)&q,    g_q);
    cudaGetSymbolAddress((void**)&v,    g_v);
    cudaGetSymbolAddress((void**)&oa,   g_oa);
    cudaGetSymbolAddress((void**)&samp, g_samp);
    cudaGetSymbolAddress((void**)&tmp,  g_tmp);
    cudaGetSymbolAddress((void**)&x,    g_x);
    cudaGetSymbolAddress((void**)&h1,   g_h1);
    cudaGetSymbolAddress((void**)&wtv,  g_wt_val);
    cudaGetSymbolAddress((void**)&wtoa, g_wt_oa);
    cudaGetSymbolAddress((void**)&wtO,  g_wt_out);
    cudaGetSymbolAddress((void**)&wt1,  g_wt_1);
    cudaGetSymbolAddress((void**)&wt2,  g_wt_2);
    cudaGetSymbolAddress((void**)&boa,  g_bias_oa);

    cudaFuncSetAttribute(gemm_mma<0>, cudaFuncAttributeMaxDynamicSharedMemorySize, GEMM_SMEM);
    cudaFuncSetAttribute(gemm_mma<1>, cudaFuncAttributeMaxDynamicSharedMemorySize, GEMM_SMEM);
    cudaFuncSetAttribute(gemm_mma<2>, cudaFuncAttributeMaxDynamicSharedMemorySize, GEMM_SMEM);

    const int M = MROWS;
    const int mblk = (M + 127) / 128;   // 416
    dim3 tb(32, 8);

    // 1. small transposes + bias concat
    transpose_small_k<<<225, tb>>>(Wval, Woff, Wattn, Wout, boff, battn,
                                   wtv, wtoa, wtO, boa);
    // 2. big transposes (W1, W2)
    transpose_big_k<<<512, tb>>>(W1, W2, wt1, wt2);
    // 3. q = src + pos
    {
        int n4 = M * DMODEL / 4;
        add_k<<<(n4 + 255) / 256, 256>>>((const float4*)src, (const float4*)pos,
                                         (float4*)q, n4);
    }
    // 4. v = src @ Wval + bval
    gemm_mma<0><<<dim3(2, mblk), 256, GEMM_SMEM>>>(src, wtv, bval, nullptr, v, M, 256, 256);
    // 5. oa = q @ [Woff|Wattn] + [boff|battn]   (fused, N=384)
    gemm_mma<0><<<dim3(3, mblk), 256, GEMM_SMEM>>>(q, wtoa, boa, nullptr, oa, M, 384, 256);
    // 6. deformable sampling + fused softmax
    sample_k<<<(M * NHEAD) / 8, 256>>>(v, oa, ref, samp);
    // 7. tmp = samp @ Wout + bout + src
    gemm_mma<2><<<dim3(2, mblk), 256, GEMM_SMEM>>>(samp, wtO, bout, src, tmp, M, 256, 256);
    // 8. x = LN(tmp)
    ln_k<<<M, 256>>>(tmp, lsg, lsb, x);
    // 9. h1 = relu(x @ W1 + b1)
    gemm_mma<1><<<dim3(8, mblk), 256, GEMM_SMEM>>>(x, wt1, b1, nullptr, h1, M, 1024, 256);
    // 10. tmp = h1 @ W2 + b2 + x
    gemm_mma<2><<<dim3(2, mblk), 256, GEMM_SMEM>>>(h1, wt2, b2, x, tmp, M, 256, 1024);
    // 11. out = LN(tmp)
    ln_k<<<M, 256>>>(tmp, lfg, lfb, out);
}

// round 10
// speedup vs baseline: 4.0232x; 1.3540x over previous
#include <cuda_runtime.h>
#include <cuda_fp16.h>
#include <cstdint>
#include <cstring>

// ---------------------------------------------------------------------------
// Problem constants
// ---------------------------------------------------------------------------
#define BATCH 4
#define LTOT  13294
#define MROWS (BATCH * LTOT)   // 53176
#define DMODEL 256
#define DFFN   1024
#define NHEAD  8
#define NLVL   4
#define NPTS   4
#define DHEAD  32

// ---------------------------------------------------------------------------
// Scratch (device globals)
// ---------------------------------------------------------------------------
__device__ __half g_src_h[MROWS * DMODEL];
__device__ __half g_q_h  [MROWS * DMODEL];
__device__ __half g_v_h  [MROWS * DMODEL];
__device__ float  g_oa   [MROWS * 384];     // offsets(256) + attn logits(128), f32
__device__ __half g_samp_h[MROWS * DMODEL];
__device__ float  g_tmp  [MROWS * DMODEL];
__device__ float  g_x    [MROWS * DMODEL];
__device__ __half g_x_h  [MROWS * DMODEL];
__device__ __half g_h1_h [MROWS * DFFN];
// transposed weights [N, K] fp16
__device__ __half g_wt_val[DMODEL * DMODEL];
__device__ __half g_wt_oa [384 * DMODEL];
__device__ __half g_wt_out[DMODEL * DMODEL];
__device__ __half g_wt_1  [DFFN * DMODEL];
__device__ __half g_wt_2  [DMODEL * DFFN];
__device__ float  g_bias_oa[384];

// ---------------------------------------------------------------------------
// Helpers
// ---------------------------------------------------------------------------
__device__ __forceinline__ uint32_t h2u(__half2 v) {
    uint32_t r;
    memcpy(&r, &v, 4);
    return r;
}

__device__ __forceinline__ void mma_16n8k16(float* d, const uint32_t* a, const uint32_t* b) {
    asm volatile(
        "mma.sync.aligned.m16n8k16.row.col.f32.f16.f16.f32 "
        "{%0,%1,%2,%3}, {%4,%5,%6,%7}, {%8,%9}, {%0,%1,%2,%3};"
        : "+f"(d[0]), "+f"(d[1]), "+f"(d[2]), "+f"(d[3])
        : "r"(a[0]), "r"(a[1]), "r"(a[2]), "r"(a[3]), "r"(b[0]), "r"(b[1]));
}

#define LDSM_X4(r0, r1, r2, r3, addr) \
    asm volatile("ldmatrix.sync.aligned.m8n8.x4.shared.b16 {%0,%1,%2,%3}, [%4];" \
        : "=r"(r0), "=r"(r1), "=r"(r2), "=r"(r3) : "r"(addr))

#define CP_ASYNC16(dst, src, nbytes) \
    asm volatile("cp.async.cg.shared.global [%0], [%1], 16, %2;" \
        :: "r"(dst), "l"(src), "r"(nbytes))
#define CP_COMMIT() asm volatile("cp.async.commit_group;")
#define CP_WAIT1()  asm volatile("cp.async.wait_group 1;")
#define CP_WAIT0()  asm volatile("cp.async.wait_group 0;")

// ---------------------------------------------------------------------------
// fp16 mma.sync GEMM, 3-stage cp.async pipeline, ldmatrix fragment loads.
// C[M,N] = A[M,K] @ Wt[N,K]^T + bias (+relu | +res)
// 128x128 CTA tile, BK=32 (fp16), 8 warps of 32x64, m16n8k16.
// MODE: 0 = bias, 1 = bias+relu, 2 = bias+residual(f32)
// OUTH: 0 = f32 output, 1 = fp16 output
// ---------------------------------------------------------------------------
#define LDSH 40                          // padded smem row stride (halfs) = 80B
#define TILE_H (128 * LDSH)              // halfs per tile buffer
#define TILE_BYTES (TILE_H * 2)          // 10240
#define GEMM_SMEM (6 * TILE_BYTES)       // 61440 bytes

template <int MODE, int OUTH>
__global__ __launch_bounds__(256)
void gemm_mma(const __half* __restrict__ A, const __half* __restrict__ Wt,
              const float* __restrict__ bias, const float* __restrict__ res,
              void* __restrict__ Cv, int M, int N, int K) {
    extern __shared__ __half smem[];
    __half* sAbase = smem;                 // 3 tiles
    __half* sBbase = smem + 3 * TILE_H;    // 3 tiles

    const int tid  = threadIdx.x;
    const int wid  = tid >> 5;
    const int lane = tid & 31;
    const int g    = lane >> 2;      // groupID 0..7
    const int tig  = lane & 3;       // thread-in-group 0..3
    const int wm   = wid >> 1;       // 0..3 (32-row slab)
    const int wn   = wid & 1;        // 0..1 (64-col slab)
    const int brow = blockIdx.y * 128;
    const int bcol = blockIdx.x * 128;
    const int NC   = K >> 5;

    // cp.async loader: 2 segments per thread per matrix (512 x 16B per tile)
    const int r0l = tid >> 2;          // rows 0..63
    const int seg = tid & 3;           // 16B segment within 64B row
    uint32_t cpA[2], cpB[2];
#pragma unroll
    for (int i = 0; i < 2; i++) {
        cpA[i] = (uint32_t)__cvta_generic_to_shared(&sAbase[(r0l + i * 64) * LDSH + seg * 8]);
        cpB[i] = (uint32_t)__cvta_generic_to_shared(&sBbase[(r0l + i * 64) * LDSH + seg * 8]);
    }

    // ldmatrix offsets (bytes, relative to tile base; +32B per k-step of 16)
    uint32_t aAddr0 = (uint32_t)__cvta_generic_to_shared(sAbase);
    uint32_t bAddr0 = (uint32_t)__cvta_generic_to_shared(sBbase);
    uint32_t aoff[2];
#pragma unroll
    for (int i = 0; i < 2; i++)
        aoff[i] = (uint32_t)(((wm * 32 + i * 16 + (lane & 15)) * LDSH + ((lane >> 4) << 3)) * 2);
    uint32_t boff[4];
#pragma unroll
    for (int j4 = 0; j4 < 4; j4++)
        boff[j4] = (uint32_t)(((wn * 64 + j4 * 16 + (lane & 7) + ((lane >> 4) << 3)) * LDSH
                               + (((lane >> 3) & 1) << 3)) * 2);

    float acc[2][8][4];
#pragma unroll
    for (int i = 0; i < 2; i++)
#pragma unroll
        for (int j = 0; j < 8; j++)
#pragma unroll
            for (int t = 0; t < 4; t++) acc[i][j][t] = 0.f;

    auto issue = [&](int ck) {
        const uint32_t bo = (uint32_t)(ck % 3) * TILE_BYTES;
        const int k0 = ck << 5;
#pragma unroll
        for (int i = 0; i < 2; i++) {
            int row = r0l + i * 64;
            CP_ASYNC16(cpA[i] + bo, &A[(size_t)(brow + row) * K + k0 + seg * 8],
                       (brow + row < M) ? 16 : 0);
            CP_ASYNC16(cpB[i] + bo, &Wt[(size_t)(bcol + row) * K + k0 + seg * 8], 16);
        }
        CP_COMMIT();
    };

    issue(0);
    if (NC > 1) issue(1);
    for (int c = 0; c < NC; ++c) {
        if (c + 1 < NC) CP_WAIT1(); else CP_WAIT0();
        __syncthreads();
        if (c + 2 < NC) issue(c + 2);

        const uint32_t tb = (uint32_t)(c % 3) * TILE_BYTES;
        const uint32_t aB = aAddr0 + tb;
        const uint32_t bB = bAddr0 + tb;
#pragma unroll
        for (int s = 0; s < 2; s++) {           // two K=16 steps per chunk
            const uint32_t ks = (uint32_t)(s * 32);  // 16 halfs = 32B
            uint32_t afr[2][4];
#pragma unroll
            for (int i = 0; i < 2; i++)
                LDSM_X4(afr[i][0], afr[i][1], afr[i][2], afr[i][3], aB + aoff[i] + ks);
#pragma unroll
            for (int j4 = 0; j4 < 4; j4++) {
                uint32_t b0[2], b1[2];
                LDSM_X4(b0[0], b0[1], b1[0], b1[1], bB + boff[j4] + ks);
                mma_16n8k16(acc[0][2 * j4 + 0], afr[0], b0);
                mma_16n8k16(acc[1][2 * j4 + 0], afr[1], b0);
                mma_16n8k16(acc[0][2 * j4 + 1], afr[0], b1);
                mma_16n8k16(acc[1][2 * j4 + 1], afr[1], b1);
            }
        }
    }

    // epilogue
    float* Cf = (float*)Cv;
    __half* Ch = (__half*)Cv;
#pragma unroll
    for (int i = 0; i < 2; i++) {
        int r0 = brow + wm * 32 + i * 16 + g;
#pragma unroll
        for (int j = 0; j < 8; j++) {
            int col = bcol + wn * 64 + j * 8 + 2 * tig;
            float b0 = __ldg(&bias[col]);
            float b1 = __ldg(&bias[col + 1]);
#pragma unroll
            for (int half_ = 0; half_ < 2; half_++) {
                int r = r0 + half_ * 8;
                if (r >= M) continue;
                float v0 = acc[i][j][2 * half_ + 0] + b0;
                float v1 = acc[i][j][2 * half_ + 1] + b1;
                if (MODE == 1) { v0 = fmaxf(v0, 0.f); v1 = fmaxf(v1, 0.f); }
                if (MODE == 2) {
                    const float2 rr = *reinterpret_cast<const float2*>(&res[(size_t)r * N + col]);
                    v0 += rr.x; v1 += rr.y;
                }
                if (OUTH) {
                    __half2 hv = __floats2half2_rn(v0, v1);
                    *reinterpret_cast<uint32_t*>(&Ch[(size_t)r * N + col]) = h2u(hv);
                } else {
                    *reinterpret_cast<float2*>(&Cf[(size_t)r * N + col]) = make_float2(v0, v1);
                }
            }
        }
    }
}

// ---------------------------------------------------------------------------
// Merged transposes -> fp16 [N,K]. 32x8 threads.
// ---------------------------------------------------------------------------
__global__ void transpose_small_k(const float* __restrict__ Wval, const float* __restrict__ Woff,
                                  const float* __restrict__ Wattn, const float* __restrict__ Wout,
                                  const float* __restrict__ boff, const float* __restrict__ battn,
                                  __half* __restrict__ wtv, __half* __restrict__ wtoa,
                                  __half* __restrict__ wtO, float* __restrict__ bias_oa) {
    __shared__ float t[32][33];
    int blk = blockIdx.x;
    int x = threadIdx.x, y = threadIdx.y;
    if (blk == 224) {
        int tt = y * 32 + x;
        for (int i = tt; i < 384; i += 256)
            bias_oa[i] = (i < 256) ? boff[i] : battn[i - 256];
        return;
    }
    const float* W; __half* Wt; int K, N, lb;
    if (blk < 64)       { W = Wval;  Wt = wtv;              K = 256; N = 256; lb = blk; }
    else if (blk < 128) { W = Woff;  Wt = wtoa;             K = 256; N = 256; lb = blk - 64; }
    else if (blk < 160) { W = Wattn; Wt = wtoa + 256 * 256; K = 256; N = 128; lb = blk - 128; }
    else                { W = Wout;  Wt = wtO;              K = 256; N = 256; lb = blk - 160; }
    int ntx = N >> 5;
    int n0 = (lb % ntx) * 32, k0 = (lb / ntx) * 32;
#pragma unroll
    for (int i = 0; i < 32; i += 8)
        t[y + i][x] = W[(size_t)(k0 + y + i) * N + n0 + x];
    __syncthreads();
#pragma unroll
    for (int i = 0; i < 32; i += 8)
        Wt[(size_t)(n0 + y + i) * K + k0 + x] = __float2half(t[x][y + i]);
}

__global__ void transpose_big_k(const float* __restrict__ W1, const float* __restrict__ W2,
                                __half* __restrict__ wt1, __half* __restrict__ wt2) {
    __shared__ float t[32][33];
    int blk = blockIdx.x;
    int x = threadIdx.x, y = threadIdx.y;
    const float* W; __half* Wt; int K, N, lb;
    if (blk < 256) { W = W1; Wt = wt1; K = 256;  N = 1024; lb = blk; }
    else           { W = W2; Wt = wt2; K = 1024; N = 256;  lb = blk - 256; }
    int ntx = N >> 5;
    int n0 = (lb % ntx) * 32, k0 = (lb / ntx) * 32;
#pragma unroll
    for (int i = 0; i < 32; i += 8)
        t[y + i][x] = W[(size_t)(k0 + y + i) * N + n0 + x];
    __syncthreads();
#pragma unroll
    for (int i = 0; i < 32; i += 8)
        Wt[(size_t)(n0 + y + i) * K + k0 + x] = __float2half(t[x][y + i]);
}

// ---------------------------------------------------------------------------
// add: q_h = h(src+pos); src_h = h(src)
// ---------------------------------------------------------------------------
__global__ void add_k(const float4* __restrict__ src4, const float4* __restrict__ pos4,
                      __half* __restrict__ qh, __half* __restrict__ srch, int n4) {
    int i = blockIdx.x * blockDim.x + threadIdx.x;
    if (i >= n4) return;
    float4 s = src4[i], p = pos4[i];
    __half2 q0 = __floats2half2_rn(s.x + p.x, s.y + p.y);
    __half2 q1 = __floats2half2_rn(s.z + p.z, s.w + p.w);
    __half2 s0 = __floats2half2_rn(s.x, s.y);
    __half2 s1 = __floats2half2_rn(s.z, s.w);
    *reinterpret_cast<uint2*>(&qh[(size_t)i * 4])   = make_uint2(h2u(q0), h2u(q1));
    *reinterpret_cast<uint2*>(&srch[(size_t)i * 4]) = make_uint2(h2u(s0), h2u(s1));
}

// ---------------------------------------------------------------------------
// Deformable sampling (fp16 v): one warp per (b,q, head-pair).
// lane = h2(1b) | p(2b) | c8(2b): 2 heads x 4 points x 4 channel-octets.
// Fused softmax over 16 (level,point) logits per head via shuffles.
// ---------------------------------------------------------------------------
__global__ __launch_bounds__(256)
void sample_k(const __half* __restrict__ v, const float* __restrict__ oa,
              const float* __restrict__ ref, __half* __restrict__ out) {
    int warp = (blockIdx.x * blockDim.x + threadIdx.x) >> 5;
    int lane = threadIdx.x & 31;
    if (warp >= MROWS * 4) return;
    int hp  = warp & 3;
    int row = warp >> 2;
    int b   = row / LTOT;
    int h2i = lane >> 4;         // head within pair
    int p   = (lane >> 2) & 3;   // point
    int c8  = lane & 3;          // channel octet (8 halfs)
    int h   = hp * 2 + h2i;

    const int HS[4] = {100, 50, 25, 13};
    const int ST[4] = {0, 10000, 12500, 13125};

    const float* offp = oa + (size_t)row * 384 + h * 32;
    const float* lgp  = oa + (size_t)row * 384 + 256 + h * 16;
    const float* refp = ref + (size_t)row * 8;

    float lg[4];
#pragma unroll
    for (int l = 0; l < 4; l++) lg[l] = __ldg(lgp + l * 4 + p);
    float mx = fmaxf(fmaxf(lg[0], lg[1]), fmaxf(lg[2], lg[3]));
    mx = fmaxf(mx, __shfl_xor_sync(0xffffffffu, mx, 4));
    mx = fmaxf(mx, __shfl_xor_sync(0xffffffffu, mx, 8));
    float e[4], s = 0.f;
#pragma unroll
    for (int l = 0; l < 4; l++) { e[l] = __expf(lg[l] - mx); s += e[l]; }
    s += __shfl_xor_sync(0xffffffffu, s, 4);
    s += __shfl_xor_sync(0xffffffffu, s, 8);
    const float inv = 1.f / s;

    float acc[8];
#pragma unroll
    for (int j = 0; j < 8; j++) acc[j] = 0.f;

#pragma unroll
    for (int l = 0; l < 4; l++) {
        const int H = HS[l], W = HS[l], S = ST[l];
        float rx = __ldg(refp + l * 2 + 0);
        float ry = __ldg(refp + l * 2 + 1);
        float ox = __ldg(offp + l * 8 + p * 2 + 0);
        float oy = __ldg(offp + l * 8 + p * 2 + 1);
        float aww = e[l] * inv;
        float x = rx * (float)W + ox - 0.5f;
        float y = ry * (float)H + oy - 0.5f;
        float x0f = floorf(x), y0f = floorf(y);
        float lx = x - x0f, ly = y - y0f;
        int x0 = (int)x0f, y0 = (int)y0f;
        float w00 = (1.f - lx) * (1.f - ly) * aww;
        float w10 = lx * (1.f - ly) * aww;
        float w01 = (1.f - lx) * ly * aww;
        float w11 = lx * ly * aww;
        bool vx0 = (x0 >= 0) && (x0 < W);
        bool vx1 = (x0 + 1 >= 0) && (x0 + 1 < W);
        bool vy0 = (y0 >= 0) && (y0 < H);
        bool vy1 = (y0 + 1 >= 0) && (y0 + 1 < H);
        // uint4 gather: 8 halfs. index stride = 32 uint4 per spatial pos.
        const uint4* vb = reinterpret_cast<const uint4*>(
            v + (size_t)(b * LTOT + S) * 256) + h * 4 + c8;
#define TAP(widx, cond, wv)                                                   \
        if (cond) {                                                           \
            uint4 t = __ldg(vb + (size_t)(widx) * 32);                        \
            __half2 hh[4];                                                    \
            memcpy(hh, &t, 16);                                               \
            _Pragma("unroll")                                                 \
            for (int j = 0; j < 4; j++) {                                     \
                float2 f = __half22float2(hh[j]);                             \
                acc[2 * j]     += (wv) * f.x;                                 \
                acc[2 * j + 1] += (wv) * f.y;                                 \
            }                                                                 \
        }
        TAP(y0 * W + x0,           vy0 && vx0, w00)
        TAP(y0 * W + x0 + 1,       vy0 && vx1, w10)
        TAP((y0 + 1) * W + x0,     vy1 && vx0, w01)
        TAP((y0 + 1) * W + x0 + 1, vy1 && vx1, w11)
#undef TAP
    }
    // reduce over point (lane bits 2,3)
#pragma unroll
    for (int j = 0; j < 8; j++) {
        acc[j] += __shfl_xor_sync(0xffffffffu, acc[j], 4);
        acc[j] += __shfl_xor_sync(0xffffffffu, acc[j], 8);
    }
    if (p == 0) {
        uint4 pk = make_uint4(h2u(__floats2half2_rn(acc[0], acc[1])),
                              h2u(__floats2half2_rn(acc[2], acc[3])),
                              h2u(__floats2half2_rn(acc[4], acc[5])),
                              h2u(__floats2half2_rn(acc[6], acc[7])));
        *reinterpret_cast<uint4*>(&out[(size_t)row * DMODEL + h * DHEAD + c8 * 8]) = pk;
    }
}

// ---------------------------------------------------------------------------
// LayerNorm over 256; optional fp16 copy
// ---------------------------------------------------------------------------
__global__ __launch_bounds__(256)
void ln_k(const float* __restrict__ in, const float* __restrict__ g,
          const float* __restrict__ b, float* __restrict__ out,
          __half* __restrict__ out_h) {
    int row = blockIdx.x;
    int t = threadIdx.x;
    float v = in[(size_t)row * DMODEL + t];
    float s = v, s2 = v * v;
#pragma unroll
    for (int o = 16; o > 0; o >>= 1) {
        s  += __shfl_xor_sync(0xffffffff, s,  o);
        s2 += __shfl_xor_sync(0xffffffff, s2, o);
    }
    __shared__ float sh[8], sh2[8];
    int wid = t >> 5, lane = t & 31;
    if (lane == 0) { sh[wid] = s; sh2[wid] = s2; }
    __syncthreads();
    float ts = 0.f, ts2 = 0.f;
#pragma unroll
    for (int i = 0; i < 8; i++) { ts += sh[i]; ts2 += sh2[i]; }
    float mu = ts * (1.f / DMODEL);
    float var = ts2 * (1.f / DMODEL) - mu * mu;
    float inv = rsqrtf(var + 1e-5f);
    float r = (v - mu) * inv * g[t] + b[t];
    out[(size_t)row * DMODEL + t] = r;
    if (out_h) out_h[(size_t)row * DMODEL + t] = __float2half(r);
}

// ---------------------------------------------------------------------------
// Launch
// ---------------------------------------------------------------------------
extern "C" void kernel_launch(void* const* d_in, const int* in_sizes, int n_in,
                              void* d_out, int out_size) {
    const float* src   = (const float*)d_in[0];
    const float* pos   = (const float*)d_in[1];
    const float* ref   = (const float*)d_in[2];
    const float* Woff  = (const float*)d_in[5];
    const float* boff  = (const float*)d_in[6];
    const float* Wattn = (const float*)d_in[7];
    const float* battn = (const float*)d_in[8];
    const float* Wval  = (const float*)d_in[9];
    const float* bval  = (const float*)d_in[10];
    const float* Wout  = (const float*)d_in[11];
    const float* bout  = (const float*)d_in[12];
    const float* lsg   = (const float*)d_in[13];
    const float* lsb   = (const float*)d_in[14];
    const float* W1    = (const float*)d_in[15];
    const float* b1    = (const float*)d_in[16];
    const float* W2    = (const float*)d_in[17];
    const float* b2    = (const float*)d_in[18];
    const float* lfg   = (const float*)d_in[19];
    const float* lfb   = (const float*)d_in[20];
    float* out = (float*)d_out;

    __half *srch, *qh, *vh, *samph, *xh, *h1h;
    __half *wtv, *wtoa, *wtO, *wt1, *wt2;
    float *oa, *tmp, *x, *boa;
    cudaGetSymbolAddress((void**)&srch,  g_src_h);
    cudaGetSymbolAddress((void**)&qh,    g_q_h);
    cudaGetSymbolAddress((void**)&vh,    g_v_h);
    cudaGetSymbolAddress((void**)&oa,    g_oa);
    cudaGetSymbolAddress((void**)&samph, g_samp_h);
    cudaGetSymbolAddress((void**)&tmp,   g_tmp);
    cudaGetSymbolAddress((void**)&x,     g_x);
    cudaGetSymbolAddress((void**)&xh,    g_x_h);
    cudaGetSymbolAddress((void**)&h1h,   g_h1_h);
    cudaGetSymbolAddress((void**)&wtv,   g_wt_val);
    cudaGetSymbolAddress((void**)&wtoa,  g_wt_oa);
    cudaGetSymbolAddress((void**)&wtO,   g_wt_out);
    cudaGetSymbolAddress((void**)&wt1,   g_wt_1);
    cudaGetSymbolAddress((void**)&wt2,   g_wt_2);
    cudaGetSymbolAddress((void**)&boa,   g_bias_oa);

    cudaFuncSetAttribute(gemm_mma<0,0>, cudaFuncAttributeMaxDynamicSharedMemorySize, GEMM_SMEM);
    cudaFuncSetAttribute(gemm_mma<0,1>, cudaFuncAttributeMaxDynamicSharedMemorySize, GEMM_SMEM);
    cudaFuncSetAttribute(gemm_mma<1,1>, cudaFuncAttributeMaxDynamicSharedMemorySize, GEMM_SMEM);
    cudaFuncSetAttribute(gemm_mma<2,0>, cudaFuncAttributeMaxDynamicSharedMemorySize, GEMM_SMEM);

    const int M = MROWS;
    const int mblk = (M + 127) / 128;   // 416
    dim3 tb(32, 8);

    // 1. small transposes + bias concat (fp16 weights)
    transpose_small_k<<<225, tb>>>(Wval, Woff, Wattn, Wout, boff, battn,
                                   wtv, wtoa, wtO, boa);
    // 2. big transposes
    transpose_big_k<<<512, tb>>>(W1, W2, wt1, wt2);
    // 3. q_h = h(src+pos); src_h = h(src)
    {
        int n4 = M * DMODEL / 4;
        add_k<<<(n4 + 255) / 256, 256>>>((const float4*)src, (const float4*)pos,
                                         qh, srch, n4);
    }
    // 4. v_h = h(src_h @ Wval + bval)
    gemm_mma<0,1><<<dim3(2, mblk), 256, GEMM_SMEM>>>(srch, wtv, bval, nullptr, vh, M, 256, 256);
    // 5. oa = q_h @ [Woff|Wattn] + [boff|battn]  (f32 out)
    gemm_mma<0,0><<<dim3(3, mblk), 256, GEMM_SMEM>>>(qh, wtoa, boa, nullptr, oa, M, 384, 256);
    // 6. sampling + fused softmax -> samp_h
    sample_k<<<(M * 4 + 7) / 8, 256>>>(vh, oa, ref, samph);
    // 7. tmp = samp_h @ Wout + bout + src (f32)
    gemm_mma<2,0><<<dim3(2, mblk), 256, GEMM_SMEM>>>(samph, wtO, bout, src, tmp, M, 256, 256);
    // 8. x = LN(tmp), x_h copy
    ln_k<<<M, 256>>>(tmp, lsg, lsb, x, xh);
    // 9. h1_h = relu(x_h @ W1 + b1)  (fp16 out)
    gemm_mma<1,1><<<dim3(8, mblk), 256, GEMM_SMEM>>>(xh, wt1, b1, nullptr, h1h, M, 1024, 256);
    // 10. tmp = h1_h @ W2 + b2 + x  (f32)
    gemm_mma<2,0><<<dim3(2, mblk), 256, GEMM_SMEM>>>(h1h, wt2, b2, x, tmp, M, 256, 1024);
    // 11. out = LN(tmp)
    ln_k<<<M, 256>>>(tmp, lfg, lfb, out, nullptr);
}